// round 4
// baseline (speedup 1.0000x reference)
#include <cuda_runtime.h>
#include <cuda_bf16.h>
#include <cstdint>

#define NN 20000    // nodes
#define D  128      // dim
#define NE 200000   // edges
#define NT 8        // timesteps
#define NTILES 157  // ceil(NN/128)
#define NRP (NTILES * 128)  // 20096 padded rows
#define PAD 136     // bf16 elems per smem row (272B stride, conflict-free ldmatrix)

// ---- static device scratch (no runtime allocation) ----
__device__ float    g_agg[(size_t)NT * NRP * D];    // per-time aggregated messages
__device__ float    g_state[(size_t)NRP * D];       // recurrent state (padded rows stay 0)
__device__ uint4    g_Wp[5 * 2 * 128 * 16];         // 5 weights x {hi,lo} x [n][k] bf16
__device__ uint16_t g_Hs_hi[(size_t)NT * NRP * D];  // H = tanh(agg@Wenc), bf16 hi
__device__ uint16_t g_Hs_lo[(size_t)NT * NRP * D];  // bf16 lo
__device__ float    g_GZ[(size_t)NT * NRP * D];     // H@Wz  (fp32 preact)
__device__ float    g_GH[(size_t)NT * NRP * D];     // H@Wh

// ---- smem layouts (bytes) ----
// henc:    X hi/lo + W hi/lo                      = 139264
// gatepre: XH hi/lo + Wz hi/lo + Wh hi/lo         = 208896
// step:    XS hi/lo + Uz hi/lo + Uh hi/lo         = 208896
#define XB_HI 0
#define XB_LO 34816
#define W0_HI 69632
#define W0_LO 104448
#define W1_HI 139264
#define W1_LO 174080
#define SMEM_HENC 139264
#define SMEM_BIG  208896

// ---------------------------------------------------------------------------
__device__ __forceinline__ uint32_t smem_u32(const void* p) {
    uint32_t a;
    asm("{ .reg .u64 t; cvta.to.shared.u64 t, %1; cvt.u32.u64 %0, t; }" : "=r"(a) : "l"(p));
    return a;
}

#define LDSM4(R, a) \
    asm volatile("ldmatrix.sync.aligned.m8n8.x4.shared.b16 {%0,%1,%2,%3}, [%4];" \
                 : "=r"((R)[0]), "=r"((R)[1]), "=r"((R)[2]), "=r"((R)[3]) : "r"(a))

#define MMA16816(d, a, b0, b1) \
    asm volatile("mma.sync.aligned.m16n8k16.row.col.f32.bf16.bf16.f32 " \
                 "{%0,%1,%2,%3},{%4,%5,%6,%7},{%8,%9},{%0,%1,%2,%3};" \
                 : "+f"((d)[0]), "+f"((d)[1]), "+f"((d)[2]), "+f"((d)[3]) \
                 : "r"((a)[0]), "r"((a)[1]), "r"((a)[2]), "r"((a)[3]), "r"(b0), "r"(b1))

__device__ __forceinline__ void split2(float x, float y, uint32_t& h, uint32_t& l) {
    __nv_bfloat16 hx = __float2bfloat16(x), hy = __float2bfloat16(y);
    float rx = x - __bfloat162float(hx);
    float ry = y - __bfloat162float(hy);
    __nv_bfloat16 lx = __float2bfloat16(rx), ly = __float2bfloat16(ry);
    h = (uint32_t)__bfloat16_as_ushort(hx) | ((uint32_t)__bfloat16_as_ushort(hy) << 16);
    l = (uint32_t)__bfloat16_as_ushort(lx) | ((uint32_t)__bfloat16_as_ushort(ly) << 16);
}

// Convert 64 fp32 -> bf16 hi/lo into padded smem row
__device__ __forceinline__ void cvt64(char* hi, char* lo, int row, int col0,
                                      const float* __restrict__ src) {
#pragma unroll
    for (int g = 0; g < 8; g++) {
        float4 a = ((const float4*)src)[g * 2];
        float4 b = ((const float4*)src)[g * 2 + 1];
        uint32_t h0, h1, h2, h3, l0, l1, l2, l3;
        split2(a.x, a.y, h0, l0);
        split2(a.z, a.w, h1, l1);
        split2(b.x, b.y, h2, l2);
        split2(b.z, b.w, h3, l3);
        uint32_t off = (uint32_t)(row * PAD + col0 + g * 8) * 2;
        *(uint4*)(hi + off) = make_uint4(h0, h1, h2, h3);
        *(uint4*)(lo + off) = make_uint4(l0, l1, l2, l3);
    }
}

// Copy pre-split weight w into smem (hi+lo, padded rows)
__device__ __forceinline__ void copy_w(char* sm, int w, int tid, int hi_off, int lo_off) {
    const uint4* s = g_Wp + (size_t)w * 4096;
#pragma unroll
    for (int i = tid; i < 4096; i += 256) {
        int sp = i >> 11, j = i & 2047, n = j >> 4, kk = j & 15;
        *(uint4*)(sm + (sp ? lo_off : hi_off) + (uint32_t)(n * PAD + kk * 8) * 2) = s[i];
    }
}

// K=128 GEMM pass, bf16x3 split: acc += X @ W^T.  Warp tile 32(m) x 64(n).
__device__ __forceinline__ void gemm_k128(float (&acc)[2][8][4],
                                          uint32_t xhi, uint32_t xlo,
                                          uint32_t whi, uint32_t wlo,
                                          int lane, int wm, int wn) {
    const int arow = wm * 32 + (lane & 15);
    const int acolo = (lane >> 4) * 8;
    const int brow = wn * 64 + (lane & 7) + ((lane >> 4) & 1) * 8;
    const int bcolo = ((lane >> 3) & 1) * 8;
#pragma unroll 1
    for (int ks = 0; ks < 8; ks++) {
        uint32_t Ah[2][4], Al[2][4], Bh[4][4], Bl[4][4];
        int ac = ks * 16 + acolo;
        int bc = ks * 16 + bcolo;
#pragma unroll
        for (int tm = 0; tm < 2; tm++) {
            uint32_t ao = (uint32_t)((arow + tm * 16) * PAD + ac) * 2;
            LDSM4(Ah[tm], xhi + ao);
            LDSM4(Al[tm], xlo + ao);
        }
#pragma unroll
        for (int g = 0; g < 4; g++) {
            uint32_t bo = (uint32_t)((brow + g * 16) * PAD + bc) * 2;
            LDSM4(Bh[g], whi + bo);
            LDSM4(Bl[g], wlo + bo);
        }
#pragma unroll
        for (int tm = 0; tm < 2; tm++)
#pragma unroll
            for (int tn = 0; tn < 8; tn++) {
                int g = tn >> 1, o = (tn & 1) * 2;
                MMA16816(acc[tm][tn], Ah[tm], Bh[g][o], Bh[g][o + 1]);
            }
#pragma unroll
        for (int tm = 0; tm < 2; tm++)
#pragma unroll
            for (int tn = 0; tn < 8; tn++) {
                int g = tn >> 1, o = (tn & 1) * 2;
                MMA16816(acc[tm][tn], Al[tm], Bh[g][o], Bh[g][o + 1]);
            }
#pragma unroll
        for (int tm = 0; tm < 2; tm++)
#pragma unroll
            for (int tn = 0; tn < 8; tn++) {
                int g = tn >> 1, o = (tn & 1) * 2;
                MMA16816(acc[tm][tn], Ah[tm], Bl[g][o], Bl[g][o + 1]);
            }
    }
}

#define ZERO_ACC(acc) \
    { _Pragma("unroll") for (int i = 0; i < 2; i++) \
      _Pragma("unroll") for (int j = 0; j < 8; j++) \
      _Pragma("unroll") for (int q = 0; q < 4; q++) (acc)[i][j][q] = 0.f; }

// ---------------------------------------------------------------------------
__global__ void prep_weights(const float* W0, const float* W1, const float* W2,
                             const float* W3, const float* W4) {
    int idx = blockIdx.x * blockDim.x + threadIdx.x;
    if (idx >= 5 * 128 * 128) return;
    int w = idx >> 14, rem = idx & 16383, n = rem >> 7, k = rem & 127;
    const float* Ws = (w == 0) ? W0 : (w == 1) ? W1 : (w == 2) ? W2 : (w == 3) ? W3 : W4;
    float v = Ws[k * 128 + n];
    __nv_bfloat16 hv = __float2bfloat16(v);
    float res = v - __bfloat162float(hv);
    __nv_bfloat16 lv = __float2bfloat16(res);
    unsigned short* base = (unsigned short*)g_Wp;
    base[(size_t)((w * 2 + 0) * 128 + n) * 128 + k] = __bfloat16_as_ushort(hv);
    base[(size_t)((w * 2 + 1) * 128 + n) * 128 + k] = __bfloat16_as_ushort(lv);
}

__global__ void zero_kernel() {
    const size_t na = (size_t)NT * NRP * D / 4;
    const size_t ns = (size_t)NRP * D / 4;
    float4 z = make_float4(0.f, 0.f, 0.f, 0.f);
    for (size_t i = (size_t)blockIdx.x * blockDim.x + threadIdx.x; i < na + ns;
         i += (size_t)gridDim.x * blockDim.x) {
        if (i < na) reinterpret_cast<float4*>(g_agg)[i] = z;
        else        reinterpret_cast<float4*>(g_state)[i - na] = z;
    }
}

__global__ void scatter_kernel(const int* __restrict__ src, const int* __restrict__ dst,
                               const int* __restrict__ etype, const int* __restrict__ etime,
                               const float* __restrict__ ew,
                               const float* __restrict__ node_emb,
                               const float* __restrict__ rel_emb) {
    int gid  = blockIdx.x * blockDim.x + threadIdx.x;
    int e    = gid >> 5;
    int lane = gid & 31;
    if (e >= NE) return;
    int t = etime[e];
    if ((unsigned)t >= NT) return;
    int s = src[e], d = dst[e], r = etype[e];
    float w = ew[e];
    float4 a = reinterpret_cast<const float4*>(node_emb + (size_t)s * D)[lane];
    float4 b = reinterpret_cast<const float4*>(rel_emb  + (size_t)r * D)[lane];
    float* o = g_agg + ((size_t)t * NRP + d) * D + lane * 4;
    asm volatile("red.global.add.v4.f32 [%0], {%1,%2,%3,%4};"
                 :: "l"(o), "f"(a.x * b.x * w), "f"(a.y * b.y * w),
                    "f"(a.z * b.z * w), "f"(a.w * b.w * w) : "memory");
}

// ---------------------------------------------------------------------------
// Batched encoder: H[t] = tanh(agg[t] @ Wenc) for all t, persistent grid,
// Wenc resident in smem. Stores H as packed bf16 hi/lo.
// ---------------------------------------------------------------------------
__global__ void __launch_bounds__(256, 1) henc_all() {
    extern __shared__ char sm[];
    uint32_t sb = smem_u32(sm);
    int tid = threadIdx.x, lane = tid & 31, wid = tid >> 5;
    int wm = wid & 3, wn = wid >> 2;

    copy_w(sm, 0, tid, W0_HI, W0_LO);  // Wenc

    for (int tt = blockIdx.x; tt < NT * NTILES; tt += gridDim.x) {
        int t = tt / NTILES, tile = tt - t * NTILES;
        __syncthreads();  // W ready (1st iter) / previous gemm done reading X
        {
            int row = tid >> 1, half = tid & 1;
            const float* pa = g_agg + ((size_t)t * NRP + tile * 128 + row) * D + half * 64;
            cvt64(sm + XB_HI, sm + XB_LO, row, half * 64, pa);
        }
        __syncthreads();
        float acc[2][8][4];
        ZERO_ACC(acc);
        gemm_k128(acc, sb + XB_HI, sb + XB_LO, sb + W0_HI, sb + W0_LO, lane, wm, wn);

        size_t base = (size_t)t * NRP + (size_t)tile * 128;
#pragma unroll
        for (int tm = 0; tm < 2; tm++)
#pragma unroll
            for (int tn = 0; tn < 8; tn++) {
                int col = wn * 64 + tn * 8 + (lane & 3) * 2;
#pragma unroll
                for (int h2 = 0; h2 < 2; h2++) {
                    int rl = wm * 32 + tm * 16 + (lane >> 2) + h2 * 8;
                    uint32_t h, l;
                    split2(tanhf(acc[tm][tn][h2 * 2]), tanhf(acc[tm][tn][h2 * 2 + 1]), h, l);
                    size_t idx = (base + rl) * D + col;
                    *(uint32_t*)(g_Hs_hi + idx) = h;
                    *(uint32_t*)(g_Hs_lo + idx) = l;
                }
            }
    }
}

// ---------------------------------------------------------------------------
// Batched gate precompute: GZ[t] = H[t]@Wz, GH[t] = H[t]@Wh for all t.
// Wz + Wh resident. Persistent grid.
// ---------------------------------------------------------------------------
__global__ void __launch_bounds__(256, 1) gatepre_all() {
    extern __shared__ char sm[];
    uint32_t sb = smem_u32(sm);
    int tid = threadIdx.x, lane = tid & 31, wid = tid >> 5;
    int wm = wid & 3, wn = wid >> 2;

    copy_w(sm, 1, tid, W0_HI, W0_LO);  // Wz
    copy_w(sm, 3, tid, W1_HI, W1_LO);  // Wh

    for (int tt = blockIdx.x; tt < NT * NTILES; tt += gridDim.x) {
        int t = tt / NTILES, tile = tt - t * NTILES;
        size_t base = (size_t)t * NRP + (size_t)tile * 128;
        __syncthreads();
        // copy packed H splits into padded smem (16 uint4 per row per split)
#pragma unroll
        for (int i = tid; i < 4096; i += 256) {
            int sp = i >> 11, j = i & 2047, r = j >> 4, c = j & 15;
            const uint16_t* s = sp ? g_Hs_lo : g_Hs_hi;
            *(uint4*)(sm + (sp ? XB_LO : XB_HI) + (uint32_t)(r * PAD + c * 8) * 2) =
                ((const uint4*)(s + (base + r) * D))[c];
        }
        __syncthreads();

        float acc[2][8][4];
        ZERO_ACC(acc);
        gemm_k128(acc, sb + XB_HI, sb + XB_LO, sb + W0_HI, sb + W0_LO, lane, wm, wn);
#pragma unroll
        for (int tm = 0; tm < 2; tm++)
#pragma unroll
            for (int tn = 0; tn < 8; tn++) {
                int col = wn * 64 + tn * 8 + (lane & 3) * 2;
#pragma unroll
                for (int h2 = 0; h2 < 2; h2++) {
                    int rl = wm * 32 + tm * 16 + (lane >> 2) + h2 * 8;
                    *(float2*)(g_GZ + (base + rl) * D + col) =
                        make_float2(acc[tm][tn][h2 * 2], acc[tm][tn][h2 * 2 + 1]);
                }
            }
        ZERO_ACC(acc);
        gemm_k128(acc, sb + XB_HI, sb + XB_LO, sb + W1_HI, sb + W1_LO, lane, wm, wn);
#pragma unroll
        for (int tm = 0; tm < 2; tm++)
#pragma unroll
            for (int tn = 0; tn < 8; tn++) {
                int col = wn * 64 + tn * 8 + (lane & 3) * 2;
#pragma unroll
                for (int h2 = 0; h2 < 2; h2++) {
                    int rl = wm * 32 + tm * 16 + (lane >> 2) + h2 * 8;
                    *(float2*)(g_GH + (base + rl) * D + col) =
                        make_float2(acc[tm][tn][h2 * 2], acc[tm][tn][h2 * 2 + 1]);
                }
            }
    }
}

// ---------------------------------------------------------------------------
// Sequential step: z = sig(GZ[t] + state@Uz + bz); c = tanh(GH[t] + state@Uh + bh)
// state' = (1-z)state + z c.   Uz + Uh resident; persistent over 157 tiles.
// ---------------------------------------------------------------------------
__global__ void __launch_bounds__(256, 1) step_kernel(int t, const float* __restrict__ bz,
                                                      const float* __restrict__ bh,
                                                      float* outp) {
    extern __shared__ char sm[];
    uint32_t sb = smem_u32(sm);
    int tid = threadIdx.x, lane = tid & 31, wid = tid >> 5;
    int wm = wid & 3, wn = wid >> 2;

    copy_w(sm, 2, tid, W0_HI, W0_LO);  // Uz
    copy_w(sm, 4, tid, W1_HI, W1_LO);  // Uh

    float* out = outp ? outp : g_state;

    for (int tile = blockIdx.x; tile < NTILES; tile += gridDim.x) {
        int row0 = tile * 128;
        __syncthreads();
        {
            int row = tid >> 1, half = tid & 1;
            const float* ps = g_state + (size_t)(row0 + row) * D + half * 64;
            cvt64(sm + XB_HI, sm + XB_LO, row, half * 64, ps);
        }
        __syncthreads();

        float accZ[2][8][4], accH[2][8][4];
        ZERO_ACC(accZ);
        ZERO_ACC(accH);
        gemm_k128(accZ, sb + XB_HI, sb + XB_LO, sb + W0_HI, sb + W0_LO, lane, wm, wn);
        gemm_k128(accH, sb + XB_HI, sb + XB_LO, sb + W1_HI, sb + W1_LO, lane, wm, wn);

        size_t base = (size_t)t * NRP + (size_t)row0;
#pragma unroll
        for (int tm = 0; tm < 2; tm++)
#pragma unroll
            for (int tn = 0; tn < 8; tn++) {
                int col = wn * 64 + tn * 8 + (lane & 3) * 2;
                float2 bzv = *(const float2*)(bz + col);
                float2 bhv = *(const float2*)(bh + col);
#pragma unroll
                for (int h2 = 0; h2 < 2; h2++) {
                    int rl = wm * 32 + tm * 16 + (lane >> 2) + h2 * 8;
                    int grow = row0 + rl;
                    if (grow < NN) {
                        float2 gz = *(const float2*)(g_GZ + (base + rl) * D + col);
                        float2 gh = *(const float2*)(g_GH + (base + rl) * D + col);
                        float2 s  = *(const float2*)(g_state + (size_t)grow * D + col);
                        float z0 = 1.f / (1.f + expf(-(gz.x + accZ[tm][tn][h2 * 2]     + bzv.x)));
                        float z1 = 1.f / (1.f + expf(-(gz.y + accZ[tm][tn][h2 * 2 + 1] + bzv.y)));
                        float c0 = tanhf(gh.x + accH[tm][tn][h2 * 2]     + bhv.x);
                        float c1 = tanhf(gh.y + accH[tm][tn][h2 * 2 + 1] + bhv.y);
                        float2 o;
                        o.x = (1.f - z0) * s.x + z0 * c0;
                        o.y = (1.f - z1) * s.y + z1 * c1;
                        *(float2*)(out + (size_t)grow * D + col) = o;
                    }
                }
            }
    }
}

// ---------------------------------------------------------------------------
extern "C" void kernel_launch(void* const* d_in, const int* in_sizes, int n_in,
                              void* d_out, int out_size) {
    const int*   ei       = (const int*)d_in[0];
    const int*   src      = ei;
    const int*   dst      = ei + NE;
    const int*   etype    = (const int*)d_in[1];
    const int*   etime    = (const int*)d_in[2];
    const float* ew       = (const float*)d_in[3];
    const float* node_emb = (const float*)d_in[4];
    const float* rel_emb  = (const float*)d_in[5];
    const float* Wenc     = (const float*)d_in[6];
    const float* Wz       = (const float*)d_in[7];
    const float* Uz       = (const float*)d_in[8];
    const float* Wh       = (const float*)d_in[9];
    const float* Uh       = (const float*)d_in[10];
    const float* bz       = (const float*)d_in[11];
    const float* bh       = (const float*)d_in[12];

    cudaFuncSetAttribute(henc_all,    cudaFuncAttributeMaxDynamicSharedMemorySize, SMEM_HENC);
    cudaFuncSetAttribute(gatepre_all, cudaFuncAttributeMaxDynamicSharedMemorySize, SMEM_BIG);
    cudaFuncSetAttribute(step_kernel, cudaFuncAttributeMaxDynamicSharedMemorySize, SMEM_BIG);

    zero_kernel<<<2048, 256>>>();
    prep_weights<<<(5 * 128 * 128 + 255) / 256, 256>>>(Wenc, Wz, Uz, Wh, Uh);
    scatter_kernel<<<(NE * 32 + 255) / 256, 256>>>(src, dst, etype, etime, ew,
                                                   node_emb, rel_emb);

    henc_all<<<148, 256, SMEM_HENC>>>();
    gatepre_all<<<148, 256, SMEM_BIG>>>();

    for (int t = 0; t < NT; t++) {
        step_kernel<<<148, 256, SMEM_BIG>>>(t, bz, bh,
                                            (t == NT - 1) ? (float*)d_out : nullptr);
    }
}

// round 5
// speedup vs baseline: 1.7080x; 1.7080x over previous
#include <cuda_runtime.h>
#include <cuda_bf16.h>
#include <cstdint>

#define NN 20000    // nodes
#define D  128      // dim
#define NE 200000   // edges
#define NT 8        // timesteps
#define NTILES 157  // ceil(NN/128)
#define NRP (NTILES * 128)  // 20096 padded rows
#define NTIL64 314  // 64-row tiles for step_all
#define PAD 136     // bf16 elems per smem row (272B stride, conflict-free ldmatrix)

// ---- static device scratch (no runtime allocation) ----
__device__ float    g_agg[(size_t)NT * NRP * D];    // per-time aggregated messages
__device__ uint4    g_Wp[5 * 2 * 128 * 16];         // 5 weights x {hi,lo} x [n][k] bf16
__device__ uint16_t g_Hs_hi[(size_t)NT * NRP * D];  // H = tanh(agg@Wenc), bf16 hi
__device__ uint16_t g_Hs_lo[(size_t)NT * NRP * D];  // bf16 lo
__device__ float    g_GZ[(size_t)NT * NRP * D];     // H@Wz  (fp32 preact)
__device__ float    g_GH[(size_t)NT * NRP * D];     // H@Wh

// ---- smem offsets (bytes) ----
// henc:    X hi/lo (69632) + Wenc hi/lo (69632) + fp32 staging (65536) = 204800
// gatepre: X hi/lo + Wz hi/lo + Wh hi/lo = 208896
// step:    X64 hi/lo (34816) + Uz hi/lo + Uh hi/lo = 174080
#define XB_HI 0
#define XB_LO 34816
#define W0_HI 69632
#define W0_LO 104448
#define W1_HI 139264
#define W1_LO 174080
#define HSTAGE 139264
#define SMEM_HENC 204800
#define SMEM_GATE 208896
#define SX_HI 0
#define SX_LO 17408
#define SW0_HI 34816
#define SW0_LO 69632
#define SW1_HI 104448
#define SW1_LO 139264
#define SMEM_STEP 174080

// ---------------------------------------------------------------------------
__device__ __forceinline__ uint32_t smem_u32(const void* p) {
    uint32_t a;
    asm("{ .reg .u64 t; cvta.to.shared.u64 t, %1; cvt.u32.u64 %0, t; }" : "=r"(a) : "l"(p));
    return a;
}

#define CP_ASYNC16(dst, src) \
    asm volatile("cp.async.cg.shared.global [%0], [%1], 16;" :: "r"(dst), "l"(src) : "memory")
#define CP_COMMIT() asm volatile("cp.async.commit_group;" ::: "memory")
#define CP_WAIT0()  asm volatile("cp.async.wait_group 0;" ::: "memory")

#define LDSM4(R, a) \
    asm volatile("ldmatrix.sync.aligned.m8n8.x4.shared.b16 {%0,%1,%2,%3}, [%4];" \
                 : "=r"((R)[0]), "=r"((R)[1]), "=r"((R)[2]), "=r"((R)[3]) : "r"(a))

#define MMA16816(d, a, b0, b1) \
    asm volatile("mma.sync.aligned.m16n8k16.row.col.f32.bf16.bf16.f32 " \
                 "{%0,%1,%2,%3},{%4,%5,%6,%7},{%8,%9},{%0,%1,%2,%3};" \
                 : "+f"((d)[0]), "+f"((d)[1]), "+f"((d)[2]), "+f"((d)[3]) \
                 : "r"((a)[0]), "r"((a)[1]), "r"((a)[2]), "r"((a)[3]), "r"(b0), "r"(b1))

__device__ __forceinline__ void split2(float x, float y, uint32_t& h, uint32_t& l) {
    __nv_bfloat16 hx = __float2bfloat16(x), hy = __float2bfloat16(y);
    float rx = x - __bfloat162float(hx);
    float ry = y - __bfloat162float(hy);
    __nv_bfloat16 lx = __float2bfloat16(rx), ly = __float2bfloat16(ry);
    h = (uint32_t)__bfloat16_as_ushort(hx) | ((uint32_t)__bfloat16_as_ushort(hy) << 16);
    l = (uint32_t)__bfloat16_as_ushort(lx) | ((uint32_t)__bfloat16_as_ushort(ly) << 16);
}

// Convert 64 fp32 -> bf16 hi/lo into padded smem row
__device__ __forceinline__ void cvt64(char* hi, char* lo, int row, int col0,
                                      const float* __restrict__ src) {
#pragma unroll
    for (int g = 0; g < 8; g++) {
        float4 a = ((const float4*)src)[g * 2];
        float4 b = ((const float4*)src)[g * 2 + 1];
        uint32_t h0, h1, h2, h3, l0, l1, l2, l3;
        split2(a.x, a.y, h0, l0);
        split2(a.z, a.w, h1, l1);
        split2(b.x, b.y, h2, l2);
        split2(b.z, b.w, h3, l3);
        uint32_t off = (uint32_t)(row * PAD + col0 + g * 8) * 2;
        *(uint4*)(hi + off) = make_uint4(h0, h1, h2, h3);
        *(uint4*)(lo + off) = make_uint4(l0, l1, l2, l3);
    }
}

// Copy pre-split weight w into smem (hi+lo, padded rows)
__device__ __forceinline__ void copy_w(char* sm, int w, int tid, int hi_off, int lo_off) {
    const uint4* s = g_Wp + (size_t)w * 4096;
#pragma unroll
    for (int i = tid; i < 4096; i += 256) {
        int sp = i >> 11, j = i & 2047, n = j >> 4, kk = j & 15;
        *(uint4*)(sm + (sp ? lo_off : hi_off) + (uint32_t)(n * PAD + kk * 8) * 2) = s[i];
    }
}

// K=128 GEMM pass, bf16x3 split, warp tile 32(m) x 64(n)
__device__ __forceinline__ void gemm_k128(float (&acc)[2][8][4],
                                          uint32_t xhi, uint32_t xlo,
                                          uint32_t whi, uint32_t wlo,
                                          int lane, int wm, int wn) {
    const int arow = wm * 32 + (lane & 15);
    const int acolo = (lane >> 4) * 8;
    const int brow = wn * 64 + (lane & 7) + ((lane >> 4) & 1) * 8;
    const int bcolo = ((lane >> 3) & 1) * 8;
#pragma unroll 2
    for (int ks = 0; ks < 8; ks++) {
        uint32_t Ah[2][4], Al[2][4], Bh[4][4], Bl[4][4];
        int ac = ks * 16 + acolo;
        int bc = ks * 16 + bcolo;
#pragma unroll
        for (int tm = 0; tm < 2; tm++) {
            uint32_t ao = (uint32_t)((arow + tm * 16) * PAD + ac) * 2;
            LDSM4(Ah[tm], xhi + ao);
            LDSM4(Al[tm], xlo + ao);
        }
#pragma unroll
        for (int g = 0; g < 4; g++) {
            uint32_t bo = (uint32_t)((brow + g * 16) * PAD + bc) * 2;
            LDSM4(Bh[g], whi + bo);
            LDSM4(Bl[g], wlo + bo);
        }
#pragma unroll
        for (int tm = 0; tm < 2; tm++)
#pragma unroll
            for (int tn = 0; tn < 8; tn++) {
                int g = tn >> 1, o = (tn & 1) * 2;
                MMA16816(acc[tm][tn], Ah[tm], Bh[g][o], Bh[g][o + 1]);
            }
#pragma unroll
        for (int tm = 0; tm < 2; tm++)
#pragma unroll
            for (int tn = 0; tn < 8; tn++) {
                int g = tn >> 1, o = (tn & 1) * 2;
                MMA16816(acc[tm][tn], Al[tm], Bh[g][o], Bh[g][o + 1]);
            }
#pragma unroll
        for (int tm = 0; tm < 2; tm++)
#pragma unroll
            for (int tn = 0; tn < 8; tn++) {
                int g = tn >> 1, o = (tn & 1) * 2;
                MMA16816(acc[tm][tn], Ah[tm], Bl[g][o], Bl[g][o + 1]);
            }
    }
}

// K=128 GEMM pass, warp tile 32(m) x 32(n)  (for 64-row tiles, 8 warps = 2x4)
__device__ __forceinline__ void gemm64(float (&acc)[2][4][4],
                                       uint32_t xhi, uint32_t xlo,
                                       uint32_t whi, uint32_t wlo,
                                       int lane, int wm, int wn) {
    const int arow = wm * 32 + (lane & 15);
    const int acolo = (lane >> 4) * 8;
    const int brow = wn * 32 + (lane & 7) + ((lane >> 4) & 1) * 8;
    const int bcolo = ((lane >> 3) & 1) * 8;
#pragma unroll 2
    for (int ks = 0; ks < 8; ks++) {
        uint32_t Ah[2][4], Al[2][4], Bh[2][4], Bl[2][4];
        int ac = ks * 16 + acolo;
        int bc = ks * 16 + bcolo;
#pragma unroll
        for (int tm = 0; tm < 2; tm++) {
            uint32_t ao = (uint32_t)((arow + tm * 16) * PAD + ac) * 2;
            LDSM4(Ah[tm], xhi + ao);
            LDSM4(Al[tm], xlo + ao);
        }
#pragma unroll
        for (int g = 0; g < 2; g++) {
            uint32_t bo = (uint32_t)((brow + g * 16) * PAD + bc) * 2;
            LDSM4(Bh[g], whi + bo);
            LDSM4(Bl[g], wlo + bo);
        }
#pragma unroll
        for (int tm = 0; tm < 2; tm++)
#pragma unroll
            for (int tn = 0; tn < 4; tn++) {
                int g = tn >> 1, o = (tn & 1) * 2;
                MMA16816(acc[tm][tn], Ah[tm], Bh[g][o], Bh[g][o + 1]);
                MMA16816(acc[tm][tn], Al[tm], Bh[g][o], Bh[g][o + 1]);
                MMA16816(acc[tm][tn], Ah[tm], Bl[g][o], Bl[g][o + 1]);
            }
    }
}

#define ZERO_ACC8(acc) \
    { _Pragma("unroll") for (int i = 0; i < 2; i++) \
      _Pragma("unroll") for (int j = 0; j < 8; j++) \
      _Pragma("unroll") for (int q = 0; q < 4; q++) (acc)[i][j][q] = 0.f; }
#define ZERO_ACC4(acc) \
    { _Pragma("unroll") for (int i = 0; i < 2; i++) \
      _Pragma("unroll") for (int j = 0; j < 4; j++) \
      _Pragma("unroll") for (int q = 0; q < 4; q++) (acc)[i][j][q] = 0.f; }

// ---------------------------------------------------------------------------
__global__ void prep_weights(const float* W0, const float* W1, const float* W2,
                             const float* W3, const float* W4) {
    int idx = blockIdx.x * blockDim.x + threadIdx.x;
    if (idx >= 5 * 128 * 128) return;
    int w = idx >> 14, rem = idx & 16383, n = rem >> 7, k = rem & 127;
    const float* Ws = (w == 0) ? W0 : (w == 1) ? W1 : (w == 2) ? W2 : (w == 3) ? W3 : W4;
    float v = Ws[k * 128 + n];
    __nv_bfloat16 hv = __float2bfloat16(v);
    float res = v - __bfloat162float(hv);
    __nv_bfloat16 lv = __float2bfloat16(res);
    unsigned short* base = (unsigned short*)g_Wp;
    base[(size_t)((w * 2 + 0) * 128 + n) * 128 + k] = __bfloat16_as_ushort(hv);
    base[(size_t)((w * 2 + 1) * 128 + n) * 128 + k] = __bfloat16_as_ushort(lv);
}

__global__ void zero_kernel() {
    const size_t na = (size_t)NT * NRP * D / 4;
    float4 z = make_float4(0.f, 0.f, 0.f, 0.f);
    for (size_t i = (size_t)blockIdx.x * blockDim.x + threadIdx.x; i < na;
         i += (size_t)gridDim.x * blockDim.x)
        reinterpret_cast<float4*>(g_agg)[i] = z;
}

__global__ void scatter_kernel(const int* __restrict__ src, const int* __restrict__ dst,
                               const int* __restrict__ etype, const int* __restrict__ etime,
                               const float* __restrict__ ew,
                               const float* __restrict__ node_emb,
                               const float* __restrict__ rel_emb) {
    int gid  = blockIdx.x * blockDim.x + threadIdx.x;
    int e    = gid >> 5;
    int lane = gid & 31;
    if (e >= NE) return;
    int t = etime[e];
    if ((unsigned)t >= NT) return;
    int s = src[e], d = dst[e], r = etype[e];
    float w = ew[e];
    float4 a = reinterpret_cast<const float4*>(node_emb + (size_t)s * D)[lane];
    float4 b = reinterpret_cast<const float4*>(rel_emb  + (size_t)r * D)[lane];
    float* o = g_agg + ((size_t)t * NRP + d) * D + lane * 4;
    asm volatile("red.global.add.v4.f32 [%0], {%1,%2,%3,%4};"
                 :: "l"(o), "f"(a.x * b.x * w), "f"(a.y * b.y * w),
                    "f"(a.z * b.z * w), "f"(a.w * b.w * w) : "memory");
}

// ---------------------------------------------------------------------------
// Batched encoder with cp.async pipelining: H[t] = tanh(agg[t] @ Wenc).
// ---------------------------------------------------------------------------
__device__ __forceinline__ void stage_agg(char* sm, uint32_t sb, int tt, int tid) {
    int t = tt / NTILES, tile = tt - t * NTILES;
    const float* src = g_agg + ((size_t)t * NRP + (size_t)tile * 128) * D;
#pragma unroll
    for (int i = tid; i < 4096; i += 256)
        CP_ASYNC16(sb + HSTAGE + i * 16, src + i * 4);
    CP_COMMIT();
}

__global__ void __launch_bounds__(256, 1) henc_all() {
    extern __shared__ char sm[];
    uint32_t sb = smem_u32(sm);
    int tid = threadIdx.x, lane = tid & 31, wid = tid >> 5;
    int wm = wid & 3, wn = wid >> 2;

    copy_w(sm, 0, tid, W0_HI, W0_LO);  // Wenc
    stage_agg(sm, sb, blockIdx.x, tid);

    for (int tt = blockIdx.x; tt < NT * NTILES; tt += gridDim.x) {
        CP_WAIT0();
        __syncthreads();  // staging ready; previous gemm done with X
        {
            int row = tid >> 1, half = tid & 1;
            const float* ps = (const float*)(sm + HSTAGE) + row * 128 + half * 64;
            cvt64(sm + XB_HI, sm + XB_LO, row, half * 64, ps);
        }
        __syncthreads();  // X ready; staging consumed
        if (tt + (int)gridDim.x < NT * NTILES) stage_agg(sm, sb, tt + gridDim.x, tid);

        float acc[2][8][4];
        ZERO_ACC8(acc);
        gemm_k128(acc, sb + XB_HI, sb + XB_LO, sb + W0_HI, sb + W0_LO, lane, wm, wn);

        int t = tt / NTILES, tile = tt - t * NTILES;
        size_t base = (size_t)t * NRP + (size_t)tile * 128;
#pragma unroll
        for (int tm = 0; tm < 2; tm++)
#pragma unroll
            for (int tn = 0; tn < 8; tn++) {
                int col = wn * 64 + tn * 8 + (lane & 3) * 2;
#pragma unroll
                for (int h2 = 0; h2 < 2; h2++) {
                    int rl = wm * 32 + tm * 16 + (lane >> 2) + h2 * 8;
                    uint32_t h, l;
                    split2(tanhf(acc[tm][tn][h2 * 2]), tanhf(acc[tm][tn][h2 * 2 + 1]), h, l);
                    size_t idx = (base + rl) * D + col;
                    *(uint32_t*)(g_Hs_hi + idx) = h;
                    *(uint32_t*)(g_Hs_lo + idx) = l;
                }
            }
    }
}

// ---------------------------------------------------------------------------
// Batched gate precompute with cp.async H staging: GZ = H@Wz, GH = H@Wh.
// ---------------------------------------------------------------------------
__device__ __forceinline__ void stage_h(char* sm, uint32_t sb, int tt, int tid) {
    int t = tt / NTILES, tile = tt - t * NTILES;
    size_t base = ((size_t)t * NRP + (size_t)tile * 128) * D;
#pragma unroll
    for (int i = tid; i < 4096; i += 256) {
        int sp = i >> 11, j = i & 2047, r = j >> 4, c = j & 15;
        const uint16_t* s = (sp ? g_Hs_lo : g_Hs_hi) + base + r * 128 + c * 8;
        CP_ASYNC16(sb + (sp ? XB_LO : XB_HI) + (uint32_t)(r * PAD + c * 8) * 2, s);
    }
    CP_COMMIT();
}

__global__ void __launch_bounds__(256, 1) gatepre_all() {
    extern __shared__ char sm[];
    uint32_t sb = smem_u32(sm);
    int tid = threadIdx.x, lane = tid & 31, wid = tid >> 5;
    int wm = wid & 3, wn = wid >> 2;

    copy_w(sm, 1, tid, W0_HI, W0_LO);  // Wz
    copy_w(sm, 3, tid, W1_HI, W1_LO);  // Wh
    stage_h(sm, sb, blockIdx.x, tid);

    for (int tt = blockIdx.x; tt < NT * NTILES; tt += gridDim.x) {
        CP_WAIT0();
        __syncthreads();

        float accZ[2][8][4], accH[2][8][4];
        ZERO_ACC8(accZ);
        ZERO_ACC8(accH);
        gemm_k128(accZ, sb + XB_HI, sb + XB_LO, sb + W0_HI, sb + W0_LO, lane, wm, wn);
        gemm_k128(accH, sb + XB_HI, sb + XB_LO, sb + W1_HI, sb + W1_LO, lane, wm, wn);
        __syncthreads();  // X consumed
        if (tt + (int)gridDim.x < NT * NTILES) stage_h(sm, sb, tt + gridDim.x, tid);

        int t = tt / NTILES, tile = tt - t * NTILES;
        size_t base = (size_t)t * NRP + (size_t)tile * 128;
#pragma unroll
        for (int tm = 0; tm < 2; tm++)
#pragma unroll
            for (int tn = 0; tn < 8; tn++) {
                int col = wn * 64 + tn * 8 + (lane & 3) * 2;
#pragma unroll
                for (int h2 = 0; h2 < 2; h2++) {
                    int rl = wm * 32 + tm * 16 + (lane >> 2) + h2 * 8;
                    *(float2*)(g_GZ + (base + rl) * D + col) =
                        make_float2(accZ[tm][tn][h2 * 2], accZ[tm][tn][h2 * 2 + 1]);
                    *(float2*)(g_GH + (base + rl) * D + col) =
                        make_float2(accH[tm][tn][h2 * 2], accH[tm][tn][h2 * 2 + 1]);
                }
            }
    }
}

// ---------------------------------------------------------------------------
// One kernel for ALL timesteps (rows independent given GZ/GH): per 64-row tile,
// state lives in registers across t; t=0 skips GEMMs (state=0).
// ---------------------------------------------------------------------------
__global__ void __launch_bounds__(256, 1) step_all(const float* __restrict__ bz,
                                                   const float* __restrict__ bh,
                                                   float* __restrict__ out) {
    extern __shared__ char sm[];
    uint32_t sb = smem_u32(sm);
    int tid = threadIdx.x, lane = tid & 31, wid = tid >> 5;
    int wm = wid & 1, wn = wid >> 1;  // 2 x 4 warp grid, 32x32 warp tiles

    copy_w(sm, 2, tid, SW0_HI, SW0_LO);  // Uz
    copy_w(sm, 4, tid, SW1_HI, SW1_LO);  // Uh
    __syncthreads();

    // per-thread fragment coordinates
    int cols[4], rowsl[2][2];
#pragma unroll
    for (int tn = 0; tn < 4; tn++) cols[tn] = wn * 32 + tn * 8 + (lane & 3) * 2;
#pragma unroll
    for (int tm = 0; tm < 2; tm++)
#pragma unroll
        for (int h2 = 0; h2 < 2; h2++)
            rowsl[tm][h2] = wm * 32 + tm * 16 + (lane >> 2) + h2 * 8;

    float2 bzv[4], bhv[4];
#pragma unroll
    for (int tn = 0; tn < 4; tn++) {
        bzv[tn] = *(const float2*)(bz + cols[tn]);
        bhv[tn] = *(const float2*)(bh + cols[tn]);
    }

    for (int tile = blockIdx.x; tile < NTIL64; tile += gridDim.x) {
        float S[2][4][4];
        ZERO_ACC4(S);

        for (int t = 0; t < NT; t++) {
            // issue GZ/GH loads first (latency hides under gemms)
            size_t base = (size_t)t * NRP + (size_t)tile * 64;
            float2 gz[2][4][2], gh[2][4][2];
#pragma unroll
            for (int tm = 0; tm < 2; tm++)
#pragma unroll
                for (int tn = 0; tn < 4; tn++)
#pragma unroll
                    for (int h2 = 0; h2 < 2; h2++) {
                        size_t idx = (base + rowsl[tm][h2]) * D + cols[tn];
                        gz[tm][tn][h2] = *(const float2*)(g_GZ + idx);
                        gh[tm][tn][h2] = *(const float2*)(g_GH + idx);
                    }

            float aZ[2][4][4], aH[2][4][4];
            ZERO_ACC4(aZ);
            ZERO_ACC4(aH);
            if (t > 0) {
                // write state fragments -> X splits
#pragma unroll
                for (int tm = 0; tm < 2; tm++)
#pragma unroll
                    for (int tn = 0; tn < 4; tn++)
#pragma unroll
                        for (int h2 = 0; h2 < 2; h2++) {
                            uint32_t h, l;
                            split2(S[tm][tn][h2 * 2], S[tm][tn][h2 * 2 + 1], h, l);
                            uint32_t off = (uint32_t)(rowsl[tm][h2] * PAD + cols[tn]) * 2;
                            *(uint32_t*)(sm + SX_HI + off) = h;
                            *(uint32_t*)(sm + SX_LO + off) = l;
                        }
                __syncthreads();
                gemm64(aZ, sb + SX_HI, sb + SX_LO, sb + SW0_HI, sb + SW0_LO, lane, wm, wn);
                gemm64(aH, sb + SX_HI, sb + SX_LO, sb + SW1_HI, sb + SW1_LO, lane, wm, wn);
                __syncthreads();  // X consumed before next t rewrites it
            }

            // GRU update in registers
#pragma unroll
            for (int tm = 0; tm < 2; tm++)
#pragma unroll
                for (int tn = 0; tn < 4; tn++)
#pragma unroll
                    for (int h2 = 0; h2 < 2; h2++) {
                        float z0 = 1.f / (1.f + expf(-(gz[tm][tn][h2].x + aZ[tm][tn][h2 * 2]     + bzv[tn].x)));
                        float z1 = 1.f / (1.f + expf(-(gz[tm][tn][h2].y + aZ[tm][tn][h2 * 2 + 1] + bzv[tn].y)));
                        float c0 = tanhf(gh[tm][tn][h2].x + aH[tm][tn][h2 * 2]     + bhv[tn].x);
                        float c1 = tanhf(gh[tm][tn][h2].y + aH[tm][tn][h2 * 2 + 1] + bhv[tn].y);
                        S[tm][tn][h2 * 2]     = (1.f - z0) * S[tm][tn][h2 * 2]     + z0 * c0;
                        S[tm][tn][h2 * 2 + 1] = (1.f - z1) * S[tm][tn][h2 * 2 + 1] + z1 * c1;
                    }
        }

        // write final state to output
#pragma unroll
        for (int tm = 0; tm < 2; tm++)
#pragma unroll
            for (int tn = 0; tn < 4; tn++)
#pragma unroll
                for (int h2 = 0; h2 < 2; h2++) {
                    int grow = tile * 64 + rowsl[tm][h2];
                    if (grow < NN)
                        *(float2*)(out + (size_t)grow * D + cols[tn]) =
                            make_float2(S[tm][tn][h2 * 2], S[tm][tn][h2 * 2 + 1]);
                }
    }
}

// ---------------------------------------------------------------------------
extern "C" void kernel_launch(void* const* d_in, const int* in_sizes, int n_in,
                              void* d_out, int out_size) {
    const int*   ei       = (const int*)d_in[0];
    const int*   src      = ei;
    const int*   dst      = ei + NE;
    const int*   etype    = (const int*)d_in[1];
    const int*   etime    = (const int*)d_in[2];
    const float* ew       = (const float*)d_in[3];
    const float* node_emb = (const float*)d_in[4];
    const float* rel_emb  = (const float*)d_in[5];
    const float* Wenc     = (const float*)d_in[6];
    const float* Wz       = (const float*)d_in[7];
    const float* Uz       = (const float*)d_in[8];
    const float* Wh       = (const float*)d_in[9];
    const float* Uh       = (const float*)d_in[10];
    const float* bz       = (const float*)d_in[11];
    const float* bh       = (const float*)d_in[12];

    cudaFuncSetAttribute(henc_all,    cudaFuncAttributeMaxDynamicSharedMemorySize, SMEM_HENC);
    cudaFuncSetAttribute(gatepre_all, cudaFuncAttributeMaxDynamicSharedMemorySize, SMEM_GATE);
    cudaFuncSetAttribute(step_all,    cudaFuncAttributeMaxDynamicSharedMemorySize, SMEM_STEP);

    zero_kernel<<<2048, 256>>>();
    prep_weights<<<(5 * 128 * 128 + 255) / 256, 256>>>(Wenc, Wz, Uz, Wh, Uh);
    scatter_kernel<<<(NE * 32 + 255) / 256, 256>>>(src, dst, etype, etime, ew,
                                                   node_emb, rel_emb);

    henc_all<<<148, 256, SMEM_HENC>>>();
    gatepre_all<<<148, 256, SMEM_GATE>>>();
    step_all<<<148, 256, SMEM_STEP>>>(bz, bh, (float*)d_out);
}

// round 6
// speedup vs baseline: 1.7850x; 1.0451x over previous
#include <cuda_runtime.h>
#include <cuda_bf16.h>
#include <cstdint>

#define NN 20000    // nodes
#define D  128      // dim
#define NE 200000   // edges
#define NT 8        // timesteps
#define NTILES 157  // 128-row tiles, ceil(NN/128)
#define NRP (NTILES * 128)  // 20096 padded rows
#define NTIL32 625  // 32-row tiles for step_all (exact: 625*32 = 20000)
#define PAD 136     // bf16 elems per smem row (272B stride, conflict-free ldmatrix)

// ---- static device scratch (no runtime allocation) ----
__device__ float    g_agg[(size_t)NT * NRP * D];    // per-time aggregated messages
__device__ uint4    g_Wp[5 * 2 * 128 * 16];         // 5 weights x {hi,lo} x [n][k] bf16
__device__ uint16_t g_Hs_hi[(size_t)NT * NRP * D];  // H = tanh(agg@Wenc), bf16 hi
__device__ uint16_t g_Hs_lo[(size_t)NT * NRP * D];  // bf16 lo
__device__ float    g_GZ[(size_t)NT * NRP * D];     // H@Wz  (fp32 preact)
__device__ float    g_GH[(size_t)NT * NRP * D];     // H@Wh

// ---- smem offsets (bytes) ----
#define XB_HI 0
#define XB_LO 34816
#define W0_HI 69632
#define W0_LO 104448
#define W1_HI 139264
#define W1_LO 174080
#define HSTAGE 139264
#define SMEM_HENC 204800   // XB + W0 + HSTAGE
#define SMEM_GATE 208896   // XB + W0 + W1
// step_all: 32-row X + Uz + Uh
#define SX_HI 0
#define SX_LO 8704
#define SW0_HI 17408
#define SW0_LO 52224
#define SW1_HI 87040
#define SW1_LO 121856
#define SMEM_STEP 156672

// ---------------------------------------------------------------------------
__device__ __forceinline__ uint32_t smem_u32(const void* p) {
    uint32_t a;
    asm("{ .reg .u64 t; cvta.to.shared.u64 t, %1; cvt.u32.u64 %0, t; }" : "=r"(a) : "l"(p));
    return a;
}

#define CP_ASYNC16(dst, src) \
    asm volatile("cp.async.cg.shared.global [%0], [%1], 16;" :: "r"(dst), "l"(src) : "memory")
#define CP_COMMIT() asm volatile("cp.async.commit_group;" ::: "memory")
#define CP_WAIT0()  asm volatile("cp.async.wait_group 0;" ::: "memory")

#define LDSM4(R, a) \
    asm volatile("ldmatrix.sync.aligned.m8n8.x4.shared.b16 {%0,%1,%2,%3}, [%4];" \
                 : "=r"((R)[0]), "=r"((R)[1]), "=r"((R)[2]), "=r"((R)[3]) : "r"(a))

#define MMA16816(d, a, b0, b1) \
    asm volatile("mma.sync.aligned.m16n8k16.row.col.f32.bf16.bf16.f32 " \
                 "{%0,%1,%2,%3},{%4,%5,%6,%7},{%8,%9},{%0,%1,%2,%3};" \
                 : "+f"((d)[0]), "+f"((d)[1]), "+f"((d)[2]), "+f"((d)[3]) \
                 : "r"((a)[0]), "r"((a)[1]), "r"((a)[2]), "r"((a)[3]), "r"(b0), "r"(b1))

__device__ __forceinline__ void split2(float x, float y, uint32_t& h, uint32_t& l) {
    __nv_bfloat16 hx = __float2bfloat16(x), hy = __float2bfloat16(y);
    float rx = x - __bfloat162float(hx);
    float ry = y - __bfloat162float(hy);
    __nv_bfloat16 lx = __float2bfloat16(rx), ly = __float2bfloat16(ry);
    h = (uint32_t)__bfloat16_as_ushort(hx) | ((uint32_t)__bfloat16_as_ushort(hy) << 16);
    l = (uint32_t)__bfloat16_as_ushort(lx) | ((uint32_t)__bfloat16_as_ushort(ly) << 16);
}

// Convert 32 fp32 -> bf16 hi/lo into padded smem row segment
__device__ __forceinline__ void cvt32(char* hi, char* lo, int row, int col0,
                                      const float* __restrict__ src) {
#pragma unroll
    for (int g = 0; g < 4; g++) {
        float4 a = ((const float4*)src)[g * 2];
        float4 b = ((const float4*)src)[g * 2 + 1];
        uint32_t h0, h1, h2, h3, l0, l1, l2, l3;
        split2(a.x, a.y, h0, l0);
        split2(a.z, a.w, h1, l1);
        split2(b.x, b.y, h2, l2);
        split2(b.z, b.w, h3, l3);
        uint32_t off = (uint32_t)(row * PAD + col0 + g * 8) * 2;
        *(uint4*)(hi + off) = make_uint4(h0, h1, h2, h3);
        *(uint4*)(lo + off) = make_uint4(l0, l1, l2, l3);
    }
}

// Copy pre-split weight w into smem (hi+lo, padded rows)
__device__ __forceinline__ void copy_w(char* sm, int w, int tid, int nthr,
                                       int hi_off, int lo_off) {
    const uint4* s = g_Wp + (size_t)w * 4096;
    for (int i = tid; i < 4096; i += nthr) {
        int sp = i >> 11, j = i & 2047, n = j >> 4, kk = j & 15;
        *(uint4*)(sm + (sp ? lo_off : hi_off) + (uint32_t)(n * PAD + kk * 8) * 2) = s[i];
    }
}

// K=128 GEMM pass, bf16x3 split, warp tile 32(m) x 32(n)
__device__ __forceinline__ void gemm_w32(float (&acc)[2][4][4],
                                         uint32_t xhi, uint32_t xlo,
                                         uint32_t whi, uint32_t wlo,
                                         int lane, int wm, int wn) {
    const int arow = wm * 32 + (lane & 15);
    const int acolo = (lane >> 4) * 8;
    const int brow = wn * 32 + (lane & 7) + ((lane >> 4) & 1) * 8;
    const int bcolo = ((lane >> 3) & 1) * 8;
#pragma unroll 2
    for (int ks = 0; ks < 8; ks++) {
        uint32_t Ah[2][4], Al[2][4], Bh[2][4], Bl[2][4];
        int ac = ks * 16 + acolo;
        int bc = ks * 16 + bcolo;
#pragma unroll
        for (int tm = 0; tm < 2; tm++) {
            uint32_t ao = (uint32_t)((arow + tm * 16) * PAD + ac) * 2;
            LDSM4(Ah[tm], xhi + ao);
            LDSM4(Al[tm], xlo + ao);
        }
#pragma unroll
        for (int g = 0; g < 2; g++) {
            uint32_t bo = (uint32_t)((brow + g * 16) * PAD + bc) * 2;
            LDSM4(Bh[g], whi + bo);
            LDSM4(Bl[g], wlo + bo);
        }
#pragma unroll
        for (int tm = 0; tm < 2; tm++)
#pragma unroll
            for (int tn = 0; tn < 4; tn++) {
                int g = tn >> 1, o = (tn & 1) * 2;
                MMA16816(acc[tm][tn], Ah[tm], Bh[g][o], Bh[g][o + 1]);
                MMA16816(acc[tm][tn], Al[tm], Bh[g][o], Bh[g][o + 1]);
                MMA16816(acc[tm][tn], Ah[tm], Bl[g][o], Bl[g][o + 1]);
            }
    }
}

// K=128 GEMM pass, warp tile 16(m) x 16(n)  (step_all, 2x8 warp grid)
__device__ __forceinline__ void gemm_w16(float (&acc)[2][4],
                                         uint32_t xhi, uint32_t xlo,
                                         uint32_t whi, uint32_t wlo,
                                         int lane, int wm, int wn) {
    const int arow = wm * 16 + (lane & 15);
    const int acolo = (lane >> 4) * 8;
    const int brow = wn * 16 + (lane & 7) + ((lane >> 4) & 1) * 8;
    const int bcolo = ((lane >> 3) & 1) * 8;
#pragma unroll 2
    for (int ks = 0; ks < 8; ks++) {
        uint32_t Ah[4], Al[4], Bh[4], Bl[4];
        uint32_t ao = (uint32_t)(arow * PAD + ks * 16 + acolo) * 2;
        uint32_t bo = (uint32_t)(brow * PAD + ks * 16 + bcolo) * 2;
        LDSM4(Ah, xhi + ao);
        LDSM4(Al, xlo + ao);
        LDSM4(Bh, whi + bo);
        LDSM4(Bl, wlo + bo);
#pragma unroll
        for (int tn = 0; tn < 2; tn++) {
            int o = tn * 2;
            MMA16816(acc[tn], Ah, Bh[o], Bh[o + 1]);
            MMA16816(acc[tn], Al, Bh[o], Bh[o + 1]);
            MMA16816(acc[tn], Ah, Bl[o], Bl[o + 1]);
        }
    }
}

#define ZERO_ACC24(acc) \
    { _Pragma("unroll") for (int i = 0; i < 2; i++) \
      _Pragma("unroll") for (int j = 0; j < 4; j++) \
      _Pragma("unroll") for (int q = 0; q < 4; q++) (acc)[i][j][q] = 0.f; }

// ---------------------------------------------------------------------------
__global__ void prep_weights(const float* W0, const float* W1, const float* W2,
                             const float* W3, const float* W4) {
    int idx = blockIdx.x * blockDim.x + threadIdx.x;
    if (idx >= 5 * 128 * 128) return;
    int w = idx >> 14, rem = idx & 16383, n = rem >> 7, k = rem & 127;
    const float* Ws = (w == 0) ? W0 : (w == 1) ? W1 : (w == 2) ? W2 : (w == 3) ? W3 : W4;
    float v = Ws[k * 128 + n];
    __nv_bfloat16 hv = __float2bfloat16(v);
    float res = v - __bfloat162float(hv);
    __nv_bfloat16 lv = __float2bfloat16(res);
    unsigned short* base = (unsigned short*)g_Wp;
    base[(size_t)((w * 2 + 0) * 128 + n) * 128 + k] = __bfloat16_as_ushort(hv);
    base[(size_t)((w * 2 + 1) * 128 + n) * 128 + k] = __bfloat16_as_ushort(lv);
}

__global__ void zero_kernel() {
    const size_t na = (size_t)NT * NRP * D / 4;
    float4 z = make_float4(0.f, 0.f, 0.f, 0.f);
    for (size_t i = (size_t)blockIdx.x * blockDim.x + threadIdx.x; i < na;
         i += (size_t)gridDim.x * blockDim.x)
        reinterpret_cast<float4*>(g_agg)[i] = z;
}

__global__ void scatter_kernel(const int* __restrict__ src, const int* __restrict__ dst,
                               const int* __restrict__ etype, const int* __restrict__ etime,
                               const float* __restrict__ ew,
                               const float* __restrict__ node_emb,
                               const float* __restrict__ rel_emb) {
    int gid  = blockIdx.x * blockDim.x + threadIdx.x;
    int e    = gid >> 5;
    int lane = gid & 31;
    if (e >= NE) return;
    int t = etime[e];
    if ((unsigned)t >= NT) return;
    int s = src[e], d = dst[e], r = etype[e];
    float w = ew[e];
    float4 a = reinterpret_cast<const float4*>(node_emb + (size_t)s * D)[lane];
    float4 b = reinterpret_cast<const float4*>(rel_emb  + (size_t)r * D)[lane];
    float* o = g_agg + ((size_t)t * NRP + d) * D + lane * 4;
    asm volatile("red.global.add.v4.f32 [%0], {%1,%2,%3,%4};"
                 :: "l"(o), "f"(a.x * b.x * w), "f"(a.y * b.y * w),
                    "f"(a.z * b.z * w), "f"(a.w * b.w * w) : "memory");
}

// ---------------------------------------------------------------------------
// Batched encoder (512 thr): H[t] = tanh(agg[t] @ Wenc), cp.async pipelined.
// ---------------------------------------------------------------------------
__device__ __forceinline__ void stage_agg(uint32_t sb, int tt, int tid) {
    int t = tt / NTILES, tile = tt - t * NTILES;
    const float* src = g_agg + ((size_t)t * NRP + (size_t)tile * 128) * D;
    for (int i = tid; i < 4096; i += 512)
        CP_ASYNC16(sb + HSTAGE + i * 16, src + i * 4);
    CP_COMMIT();
}

__global__ void __launch_bounds__(512, 1) henc_all() {
    extern __shared__ char sm[];
    uint32_t sb = smem_u32(sm);
    int tid = threadIdx.x, lane = tid & 31, wid = tid >> 5;
    int wm = wid & 3, wn = wid >> 2;   // 4 x 4, 32x32 warp tiles

    copy_w(sm, 0, tid, 512, W0_HI, W0_LO);  // Wenc
    stage_agg(sb, blockIdx.x, tid);

    for (int tt = blockIdx.x; tt < NT * NTILES; tt += gridDim.x) {
        CP_WAIT0();
        __syncthreads();  // staging ready; prev gemm done with X
        {
            int row = tid >> 2, q = (tid & 3) * 32;
            cvt32(sm + XB_HI, sm + XB_LO, row, q,
                  (const float*)(sm + HSTAGE) + row * 128 + q);
        }
        __syncthreads();  // X ready; staging consumed
        if (tt + (int)gridDim.x < NT * NTILES) stage_agg(sb, tt + gridDim.x, tid);

        float acc[2][4][4];
        ZERO_ACC24(acc);
        gemm_w32(acc, sb + XB_HI, sb + XB_LO, sb + W0_HI, sb + W0_LO, lane, wm, wn);

        int t = tt / NTILES, tile = tt - t * NTILES;
        size_t base = (size_t)t * NRP + (size_t)tile * 128;
#pragma unroll
        for (int tm = 0; tm < 2; tm++)
#pragma unroll
            for (int tn = 0; tn < 4; tn++) {
                int col = wn * 32 + tn * 8 + (lane & 3) * 2;
#pragma unroll
                for (int h2 = 0; h2 < 2; h2++) {
                    int rl = wm * 32 + tm * 16 + (lane >> 2) + h2 * 8;
                    uint32_t h, l;
                    split2(tanhf(acc[tm][tn][h2 * 2]), tanhf(acc[tm][tn][h2 * 2 + 1]), h, l);
                    size_t idx = (base + rl) * D + col;
                    *(uint32_t*)(g_Hs_hi + idx) = h;
                    *(uint32_t*)(g_Hs_lo + idx) = l;
                }
            }
    }
}

// ---------------------------------------------------------------------------
// Batched gate precompute (512 thr): GZ = H@Wz, GH = H@Wh. Sequential accs
// (one live at a time) to stay under 128 regs.
// ---------------------------------------------------------------------------
__device__ __forceinline__ void stage_h(uint32_t sb, int tt, int tid) {
    int t = tt / NTILES, tile = tt - t * NTILES;
    size_t base = ((size_t)t * NRP + (size_t)tile * 128) * D;
    for (int i = tid; i < 4096; i += 512) {
        int sp = i >> 11, j = i & 2047, r = j >> 4, c = j & 15;
        const uint16_t* s = (sp ? g_Hs_lo : g_Hs_hi) + base + r * 128 + c * 8;
        CP_ASYNC16(sb + (sp ? XB_LO : XB_HI) + (uint32_t)(r * PAD + c * 8) * 2, s);
    }
    CP_COMMIT();
}

__global__ void __launch_bounds__(512, 1) gatepre_all() {
    extern __shared__ char sm[];
    uint32_t sb = smem_u32(sm);
    int tid = threadIdx.x, lane = tid & 31, wid = tid >> 5;
    int wm = wid & 3, wn = wid >> 2;

    copy_w(sm, 1, tid, 512, W0_HI, W0_LO);  // Wz
    copy_w(sm, 3, tid, 512, W1_HI, W1_LO);  // Wh
    stage_h(sb, blockIdx.x, tid);

    for (int tt = blockIdx.x; tt < NT * NTILES; tt += gridDim.x) {
        CP_WAIT0();
        __syncthreads();

        int t = tt / NTILES, tile = tt - t * NTILES;
        size_t base = (size_t)t * NRP + (size_t)tile * 128;

        float acc[2][4][4];
        ZERO_ACC24(acc);
        gemm_w32(acc, sb + XB_HI, sb + XB_LO, sb + W0_HI, sb + W0_LO, lane, wm, wn);
#pragma unroll
        for (int tm = 0; tm < 2; tm++)
#pragma unroll
            for (int tn = 0; tn < 4; tn++) {
                int col = wn * 32 + tn * 8 + (lane & 3) * 2;
#pragma unroll
                for (int h2 = 0; h2 < 2; h2++) {
                    int rl = wm * 32 + tm * 16 + (lane >> 2) + h2 * 8;
                    *(float2*)(g_GZ + (base + rl) * D + col) =
                        make_float2(acc[tm][tn][h2 * 2], acc[tm][tn][h2 * 2 + 1]);
                }
            }

        ZERO_ACC24(acc);
        gemm_w32(acc, sb + XB_HI, sb + XB_LO, sb + W1_HI, sb + W1_LO, lane, wm, wn);
        __syncthreads();  // X consumed by both gemms
        if (tt + (int)gridDim.x < NT * NTILES) stage_h(sb, tt + gridDim.x, tid);
#pragma unroll
        for (int tm = 0; tm < 2; tm++)
#pragma unroll
            for (int tn = 0; tn < 4; tn++) {
                int col = wn * 32 + tn * 8 + (lane & 3) * 2;
#pragma unroll
                for (int h2 = 0; h2 < 2; h2++) {
                    int rl = wm * 32 + tm * 16 + (lane >> 2) + h2 * 8;
                    *(float2*)(g_GH + (base + rl) * D + col) =
                        make_float2(acc[tm][tn][h2 * 2], acc[tm][tn][h2 * 2 + 1]);
                }
            }
    }
}

// ---------------------------------------------------------------------------
// All timesteps in one kernel (512 thr): 32-row tiles (625 exact), state in
// registers across t; t=0 skips GEMMs (state=0). Warp grid 2(m) x 8(n).
// ---------------------------------------------------------------------------
__global__ void __launch_bounds__(512, 1) step_all(const float* __restrict__ bz,
                                                   const float* __restrict__ bh,
                                                   float* __restrict__ out) {
    extern __shared__ char sm[];
    uint32_t sb = smem_u32(sm);
    int tid = threadIdx.x, lane = tid & 31, wid = tid >> 5;
    int wm = wid & 1, wn = wid >> 1;

    copy_w(sm, 2, tid, 512, SW0_HI, SW0_LO);  // Uz
    copy_w(sm, 4, tid, 512, SW1_HI, SW1_LO);  // Uh
    __syncthreads();

    int cols[2], rowsl[2];
#pragma unroll
    for (int tn = 0; tn < 2; tn++) cols[tn] = wn * 16 + tn * 8 + (lane & 3) * 2;
#pragma unroll
    for (int h2 = 0; h2 < 2; h2++) rowsl[h2] = wm * 16 + (lane >> 2) + h2 * 8;

    float2 bzv[2], bhv[2];
#pragma unroll
    for (int tn = 0; tn < 2; tn++) {
        bzv[tn] = *(const float2*)(bz + cols[tn]);
        bhv[tn] = *(const float2*)(bh + cols[tn]);
    }

    for (int tile = blockIdx.x; tile < NTIL32; tile += gridDim.x) {
        float S[2][4];
#pragma unroll
        for (int tn = 0; tn < 2; tn++)
#pragma unroll
            for (int q = 0; q < 4; q++) S[tn][q] = 0.f;

        for (int t = 0; t < NT; t++) {
            size_t base = (size_t)t * NRP + (size_t)tile * 32;
            float2 gz[2][2], gh[2][2];
#pragma unroll
            for (int tn = 0; tn < 2; tn++)
#pragma unroll
                for (int h2 = 0; h2 < 2; h2++) {
                    size_t idx = (base + rowsl[h2]) * D + cols[tn];
                    gz[tn][h2] = *(const float2*)(g_GZ + idx);
                    gh[tn][h2] = *(const float2*)(g_GH + idx);
                }

            float aZ[2][4], aH[2][4];
#pragma unroll
            for (int tn = 0; tn < 2; tn++)
#pragma unroll
                for (int q = 0; q < 4; q++) { aZ[tn][q] = 0.f; aH[tn][q] = 0.f; }

            if (t > 0) {
#pragma unroll
                for (int tn = 0; tn < 2; tn++)
#pragma unroll
                    for (int h2 = 0; h2 < 2; h2++) {
                        uint32_t h, l;
                        split2(S[tn][h2 * 2], S[tn][h2 * 2 + 1], h, l);
                        uint32_t off = (uint32_t)(rowsl[h2] * PAD + cols[tn]) * 2;
                        *(uint32_t*)(sm + SX_HI + off) = h;
                        *(uint32_t*)(sm + SX_LO + off) = l;
                    }
                __syncthreads();
                gemm_w16(aZ, sb + SX_HI, sb + SX_LO, sb + SW0_HI, sb + SW0_LO, lane, wm, wn);
                gemm_w16(aH, sb + SX_HI, sb + SX_LO, sb + SW1_HI, sb + SW1_LO, lane, wm, wn);
                __syncthreads();  // X consumed before next t rewrites
            }

#pragma unroll
            for (int tn = 0; tn < 2; tn++)
#pragma unroll
                for (int h2 = 0; h2 < 2; h2++) {
                    float z0 = 1.f / (1.f + expf(-(gz[tn][h2].x + aZ[tn][h2 * 2]     + bzv[tn].x)));
                    float z1 = 1.f / (1.f + expf(-(gz[tn][h2].y + aZ[tn][h2 * 2 + 1] + bzv[tn].y)));
                    float c0 = tanhf(gh[tn][h2].x + aH[tn][h2 * 2]     + bhv[tn].x);
                    float c1 = tanhf(gh[tn][h2].y + aH[tn][h2 * 2 + 1] + bhv[tn].y);
                    S[tn][h2 * 2]     = (1.f - z0) * S[tn][h2 * 2]     + z0 * c0;
                    S[tn][h2 * 2 + 1] = (1.f - z1) * S[tn][h2 * 2 + 1] + z1 * c1;
                }
        }

#pragma unroll
        for (int tn = 0; tn < 2; tn++)
#pragma unroll
            for (int h2 = 0; h2 < 2; h2++) {
                int grow = tile * 32 + rowsl[h2];
                *(float2*)(out + (size_t)grow * D + cols[tn]) =
                    make_float2(S[tn][h2 * 2], S[tn][h2 * 2 + 1]);
            }
    }
}

// ---------------------------------------------------------------------------
extern "C" void kernel_launch(void* const* d_in, const int* in_sizes, int n_in,
                              void* d_out, int out_size) {
    const int*   ei       = (const int*)d_in[0];
    const int*   src      = ei;
    const int*   dst      = ei + NE;
    const int*   etype    = (const int*)d_in[1];
    const int*   etime    = (const int*)d_in[2];
    const float* ew       = (const float*)d_in[3];
    const float* node_emb = (const float*)d_in[4];
    const float* rel_emb  = (const float*)d_in[5];
    const float* Wenc     = (const float*)d_in[6];
    const float* Wz       = (const float*)d_in[7];
    const float* Uz       = (const float*)d_in[8];
    const float* Wh       = (const float*)d_in[9];
    const float* Uh       = (const float*)d_in[10];
    const float* bz       = (const float*)d_in[11];
    const float* bh       = (const float*)d_in[12];

    cudaFuncSetAttribute(henc_all,    cudaFuncAttributeMaxDynamicSharedMemorySize, SMEM_HENC);
    cudaFuncSetAttribute(gatepre_all, cudaFuncAttributeMaxDynamicSharedMemorySize, SMEM_GATE);
    cudaFuncSetAttribute(step_all,    cudaFuncAttributeMaxDynamicSharedMemorySize, SMEM_STEP);

    zero_kernel<<<2048, 256>>>();
    prep_weights<<<(5 * 128 * 128 + 255) / 256, 256>>>(Wenc, Wz, Uz, Wh, Uh);
    scatter_kernel<<<(NE * 32 + 255) / 256, 256>>>(src, dst, etype, etime, ew,
                                                   node_emb, rel_emb);

    henc_all<<<148, 512, SMEM_HENC>>>();
    gatepre_all<<<148, 512, SMEM_GATE>>>();
    step_all<<<148, 512, SMEM_STEP>>>(bz, bh, (float*)d_out);
}

// round 7
// speedup vs baseline: 1.9217x; 1.0766x over previous
#include <cuda_runtime.h>
#include <cuda_bf16.h>
#include <cstdint>

#define NN 20000    // nodes
#define D  128      // dim
#define NE 200000   // edges
#define NT 8        // timesteps
#define NRP 20096   // padded rows (157*128)
#define NTIL64 314  // 64-row tiles (NRP/64)
#define NTT (NT * NTIL64)   // 2512 (t,tile) pairs for enc_gates
#define NTIL32 625  // 32-row tiles for step_all (exact: 625*32 = 20000)
#define PAD 136     // bf16 elems per padded smem row (step_all layout)

// ---- static device scratch (no runtime allocation) ----
__device__ float g_agg[(size_t)NT * NRP * D];  // per-time aggregated messages
__device__ uint4 g_Wp[5 * 2 * 128 * 16];       // 5 weights x {hi,lo} x [n][k] bf16 linear
__device__ float g_GZ[(size_t)NT * NRP * D];   // H@Wz (fp32 preact)
__device__ float g_GH[(size_t)NT * NRP * D];   // H@Wh

// ---- enc_gates smem (XOR-swizzled 256B rows) ----
#define EX_HI 0
#define EX_LO 16384
#define EWE_HI 32768
#define EWE_LO 65536
#define EWZ_HI 98304
#define EWZ_LO 131072
#define EWH_HI 163840
#define EWH_LO 196608
#define SMEM_ENC 229376

// ---- step_all smem (padded rows for X/W + GZ/GH staging) ----
#define SX_HI 0
#define SX_LO 8704
#define SW0_HI 17408
#define SW0_LO 52224
#define SW1_HI 87040
#define SW1_LO 121856
#define GST 156672
#define GROW 528              // staged row stride (bytes): 512 + 16 pad
#define GHALF (32 * GROW)     // 16896: one GZ or GH tile
#define GBUF (2 * GHALF)      // 33792: GZ+GH for one t
#define SMEM_STEP (GST + 2 * GBUF)   // 224256

// ---------------------------------------------------------------------------
__device__ __forceinline__ uint32_t smem_u32(const void* p) {
    uint32_t a;
    asm("{ .reg .u64 t; cvta.to.shared.u64 t, %1; cvt.u32.u64 %0, t; }" : "=r"(a) : "l"(p));
    return a;
}

#define CP_ASYNC16(dst, src) \
    asm volatile("cp.async.cg.shared.global [%0], [%1], 16;" :: "r"(dst), "l"(src) : "memory")
#define CP_COMMIT() asm volatile("cp.async.commit_group;" ::: "memory")
#define CP_WAIT0()  asm volatile("cp.async.wait_group 0;" ::: "memory")
#define CP_WAIT1()  asm volatile("cp.async.wait_group 1;" ::: "memory")

#define LDSM4(R, a) \
    asm volatile("ldmatrix.sync.aligned.m8n8.x4.shared.b16 {%0,%1,%2,%3}, [%4];" \
                 : "=r"((R)[0]), "=r"((R)[1]), "=r"((R)[2]), "=r"((R)[3]) : "r"(a))

#define MMA16816(d, a, b0, b1) \
    asm volatile("mma.sync.aligned.m16n8k16.row.col.f32.bf16.bf16.f32 " \
                 "{%0,%1,%2,%3},{%4,%5,%6,%7},{%8,%9},{%0,%1,%2,%3};" \
                 : "+f"((d)[0]), "+f"((d)[1]), "+f"((d)[2]), "+f"((d)[3]) \
                 : "r"((a)[0]), "r"((a)[1]), "r"((a)[2]), "r"((a)[3]), "r"(b0), "r"(b1))

__device__ __forceinline__ void split2(float x, float y, uint32_t& h, uint32_t& l) {
    __nv_bfloat16 hx = __float2bfloat16(x), hy = __float2bfloat16(y);
    float rx = x - __bfloat162float(hx);
    float ry = y - __bfloat162float(hy);
    __nv_bfloat16 lx = __float2bfloat16(rx), ly = __float2bfloat16(ry);
    h = (uint32_t)__bfloat16_as_ushort(hx) | ((uint32_t)__bfloat16_as_ushort(hy) << 16);
    l = (uint32_t)__bfloat16_as_ushort(lx) | ((uint32_t)__bfloat16_as_ushort(ly) << 16);
}

// ---------------------------------------------------------------------------
// Weight prep: g_Wp[w][sp][n][k] = bf16 split of W[k][n] (linear layout)
// ---------------------------------------------------------------------------
__global__ void prep_weights(const float* W0, const float* W1, const float* W2,
                             const float* W3, const float* W4) {
    int idx = blockIdx.x * blockDim.x + threadIdx.x;
    if (idx >= 5 * 128 * 128) return;
    int w = idx >> 14, rem = idx & 16383, n = rem >> 7, k = rem & 127;
    const float* Ws = (w == 0) ? W0 : (w == 1) ? W1 : (w == 2) ? W2 : (w == 3) ? W3 : W4;
    float v = Ws[k * 128 + n];
    __nv_bfloat16 hv = __float2bfloat16(v);
    float res = v - __bfloat162float(hv);
    __nv_bfloat16 lv = __float2bfloat16(res);
    unsigned short* base = (unsigned short*)g_Wp;
    base[(size_t)((w * 2 + 0) * 128 + n) * 128 + k] = __bfloat16_as_ushort(hv);
    base[(size_t)((w * 2 + 1) * 128 + n) * 128 + k] = __bfloat16_as_ushort(lv);
}

__global__ void zero_kernel() {
    const size_t na = (size_t)NT * NRP * D / 4;
    float4 z = make_float4(0.f, 0.f, 0.f, 0.f);
    for (size_t i = (size_t)blockIdx.x * blockDim.x + threadIdx.x; i < na;
         i += (size_t)gridDim.x * blockDim.x)
        reinterpret_cast<float4*>(g_agg)[i] = z;
}

__global__ void scatter_kernel(const int* __restrict__ src, const int* __restrict__ dst,
                               const int* __restrict__ etype, const int* __restrict__ etime,
                               const float* __restrict__ ew,
                               const float* __restrict__ node_emb,
                               const float* __restrict__ rel_emb) {
    int gid  = blockIdx.x * blockDim.x + threadIdx.x;
    int e    = gid >> 5;
    int lane = gid & 31;
    if (e >= NE) return;
    int t = etime[e];
    if ((unsigned)t >= NT) return;
    int s = src[e], d = dst[e], r = etype[e];
    float w = ew[e];
    float4 a = reinterpret_cast<const float4*>(node_emb + (size_t)s * D)[lane];
    float4 b = reinterpret_cast<const float4*>(rel_emb  + (size_t)r * D)[lane];
    float* o = g_agg + ((size_t)t * NRP + d) * D + lane * 4;
    asm volatile("red.global.add.v4.f32 [%0], {%1,%2,%3,%4};"
                 :: "l"(o), "f"(a.x * b.x * w), "f"(a.y * b.y * w),
                    "f"(a.z * b.z * w), "f"(a.w * b.w * w) : "memory");
}

// ---------------------------------------------------------------------------
// enc_gates: fused H = tanh(agg@Wenc) (smem-only), GZ = H@Wz, GH = H@Wh.
// 64-row tiles, 512 thr, XOR-swizzled 256B-row smem (chunk ^= row&7).
// ---------------------------------------------------------------------------
// Copy weight w from linear g_Wp into swizzled smem buffers
__device__ __forceinline__ void copy_w_swz(char* sm_, int w, int tid,
                                           int hi_off, int lo_off) {
    const uint4* s = g_Wp + (size_t)w * 4096;
    for (int i = tid; i < 4096; i += 512) {
        int sp = i >> 11, j = i & 2047, n = j >> 4, c = j & 15;
        uint32_t off = (uint32_t)(n * 256) + (((c ^ (n & 7)) & 15) << 4);
        *(uint4*)(sm_ + (sp ? lo_off : hi_off) + off) = s[i];
    }
}

// K=128 bf16x3 GEMM over 64-row swizzled X: warp grid 2(m) x 8(n), tile 32x16
__device__ __forceinline__ void gemm64sw(float (&acc)[2][2][4],
                                         uint32_t xhi, uint32_t xlo,
                                         uint32_t whi, uint32_t wlo,
                                         int lane, int wm, int wn) {
    int ar = wm * 32 + (lane & 15);
    int ach = lane >> 4;
    int brow = wn * 16 + (lane & 7) + ((lane >> 4) & 1) * 8;
    int bch = (lane >> 3) & 1;
    uint32_t ab0 = (uint32_t)(ar * 256), ab1 = (uint32_t)((ar + 16) * 256);
    int am = ar & 7;          // (ar+16)&7 == am
    uint32_t bb = (uint32_t)(brow * 256);
    int bm = brow & 7;
#pragma unroll 2
    for (int ks = 0; ks < 8; ks++) {
        uint32_t Ah[2][4], Al[2][4], Bh[4], Bl[4];
        uint32_t ao = (uint32_t)((((ks * 2 + ach) ^ am) & 15) << 4);
        uint32_t bo = (uint32_t)((((ks * 2 + bch) ^ bm) & 15) << 4);
        LDSM4(Ah[0], xhi + ab0 + ao);
        LDSM4(Al[0], xlo + ab0 + ao);
        LDSM4(Ah[1], xhi + ab1 + ao);
        LDSM4(Al[1], xlo + ab1 + ao);
        LDSM4(Bh, whi + bb + bo);
        LDSM4(Bl, wlo + bb + bo);
#pragma unroll
        for (int tm = 0; tm < 2; tm++)
#pragma unroll
            for (int tn = 0; tn < 2; tn++) {
                int o = tn * 2;
                MMA16816(acc[tm][tn], Ah[tm], Bh[o], Bh[o + 1]);
                MMA16816(acc[tm][tn], Al[tm], Bh[o], Bh[o + 1]);
                MMA16816(acc[tm][tn], Ah[tm], Bl[o], Bl[o + 1]);
            }
    }
}

#define ZERO_ACC224(acc) \
    { _Pragma("unroll") for (int i = 0; i < 2; i++) \
      _Pragma("unroll") for (int j = 0; j < 2; j++) \
      _Pragma("unroll") for (int q = 0; q < 4; q++) (acc)[i][j][q] = 0.f; }

__global__ void __launch_bounds__(512, 1) enc_gates() {
    extern __shared__ char sm[];
    uint32_t sb = smem_u32(sm);
    int tid = threadIdx.x, lane = tid & 31, wid = tid >> 5;
    int wm = wid & 1, wn = wid >> 1;     // 2 x 8 warp grid

    copy_w_swz(sm, 0, tid, EWE_HI, EWE_LO);  // Wenc
    copy_w_swz(sm, 1, tid, EWZ_HI, EWZ_LO);  // Wz
    copy_w_swz(sm, 3, tid, EWH_HI, EWH_LO);  // Wh

    // per-thread agg load coords: row = tid>>3 (0..63), seg = (tid&7)*16
    int xrow = tid >> 3, xseg = (tid & 7) * 16;
    int xc0 = xseg >> 3;   // first 16B chunk index

    // prefetch first tile's agg into registers
    float4 pf[4];
    {
        int tt = blockIdx.x;
        int t = tt / NTIL64, tile = tt - t * NTIL64;
        const float4* s = (const float4*)(g_agg + ((size_t)t * NRP + tile * 64 + xrow) * D + xseg);
#pragma unroll
        for (int q = 0; q < 4; q++) pf[q] = s[q];
    }

    for (int tt = blockIdx.x; tt < NTT; tt += gridDim.x) {
        int t = tt / NTIL64, tile = tt - t * NTIL64;

        __syncthreads();  // X free (prev iter Z/H gemms done with H)
        // convert prefetched agg -> swizzled X splits
#pragma unroll
        for (int g = 0; g < 2; g++) {
            float4 a = pf[g * 2], b = pf[g * 2 + 1];
            uint32_t h0, h1, h2, h3, l0, l1, l2, l3;
            split2(a.x, a.y, h0, l0);
            split2(a.z, a.w, h1, l1);
            split2(b.x, b.y, h2, l2);
            split2(b.z, b.w, h3, l3);
            uint32_t off = (uint32_t)(xrow * 256) + ((((xc0 + g) ^ (xrow & 7)) & 15) << 4);
            *(uint4*)(sm + EX_HI + off) = make_uint4(h0, h1, h2, h3);
            *(uint4*)(sm + EX_LO + off) = make_uint4(l0, l1, l2, l3);
        }
        __syncthreads();  // X ready

        // encoder GEMM
        float acc[2][2][4];
        ZERO_ACC224(acc);
        gemm64sw(acc, sb + EX_HI, sb + EX_LO, sb + EWE_HI, sb + EWE_LO, lane, wm, wn);
        __syncthreads();  // all warps done reading agg X

        // tanh + split H back into X buffers (swizzled)
#pragma unroll
        for (int tm = 0; tm < 2; tm++)
#pragma unroll
            for (int tn = 0; tn < 2; tn++) {
                int c = wn * 16 + tn * 8 + (lane & 3) * 2;
#pragma unroll
                for (int h2i = 0; h2i < 2; h2i++) {
                    int r = wm * 32 + tm * 16 + (lane >> 2) + h2i * 8;
                    uint32_t h, l;
                    split2(tanhf(acc[tm][tn][h2i * 2]), tanhf(acc[tm][tn][h2i * 2 + 1]), h, l);
                    uint32_t off = (uint32_t)(r * 256) + ((((c >> 3) ^ (r & 7)) & 15) << 4)
                                 + (uint32_t)((c & 7) * 2);
                    *(uint32_t*)(sm + EX_HI + off) = h;
                    *(uint32_t*)(sm + EX_LO + off) = l;
                }
            }
        __syncthreads();  // H ready

        // prefetch next tile's agg (latency hides under Z/H gemms)
        if (tt + (int)gridDim.x < NTT) {
            int nt2 = tt + gridDim.x;
            int t2 = nt2 / NTIL64, tile2 = nt2 - t2 * NTIL64;
            const float4* s = (const float4*)(g_agg + ((size_t)t2 * NRP + tile2 * 64 + xrow) * D + xseg);
#pragma unroll
            for (int q = 0; q < 4; q++) pf[q] = s[q];
        }

        size_t base = (size_t)t * NRP + (size_t)tile * 64;

        // GZ = H @ Wz
        ZERO_ACC224(acc);
        gemm64sw(acc, sb + EX_HI, sb + EX_LO, sb + EWZ_HI, sb + EWZ_LO, lane, wm, wn);
#pragma unroll
        for (int tm = 0; tm < 2; tm++)
#pragma unroll
            for (int tn = 0; tn < 2; tn++) {
                int c = wn * 16 + tn * 8 + (lane & 3) * 2;
#pragma unroll
                for (int h2i = 0; h2i < 2; h2i++) {
                    int r = wm * 32 + tm * 16 + (lane >> 2) + h2i * 8;
                    *(float2*)(g_GZ + (base + r) * D + c) =
                        make_float2(acc[tm][tn][h2i * 2], acc[tm][tn][h2i * 2 + 1]);
                }
            }

        // GH = H @ Wh
        ZERO_ACC224(acc);
        gemm64sw(acc, sb + EX_HI, sb + EX_LO, sb + EWH_HI, sb + EWH_LO, lane, wm, wn);
#pragma unroll
        for (int tm = 0; tm < 2; tm++)
#pragma unroll
            for (int tn = 0; tn < 2; tn++) {
                int c = wn * 16 + tn * 8 + (lane & 3) * 2;
#pragma unroll
                for (int h2i = 0; h2i < 2; h2i++) {
                    int r = wm * 32 + tm * 16 + (lane >> 2) + h2i * 8;
                    *(float2*)(g_GH + (base + r) * D + c) =
                        make_float2(acc[tm][tn][h2i * 2], acc[tm][tn][h2i * 2 + 1]);
                }
            }
    }
}

// ---------------------------------------------------------------------------
// step_all: all timesteps, state in registers; Uz/Uh resident (padded layout);
// GZ/GH tiles double-buffered via cp.async.
// ---------------------------------------------------------------------------
__device__ __forceinline__ void copy_w_pad(char* sm_, int w, int tid,
                                           int hi_off, int lo_off) {
    const uint4* s = g_Wp + (size_t)w * 4096;
    for (int i = tid; i < 4096; i += 512) {
        int sp = i >> 11, j = i & 2047, n = j >> 4, kk = j & 15;
        *(uint4*)(sm_ + (sp ? lo_off : hi_off) + (uint32_t)(n * PAD + kk * 8) * 2) = s[i];
    }
}

// K=128 GEMM, warp tile 16x16 (2x8 warp grid), padded layout
__device__ __forceinline__ void gemm_w16(float (&acc)[2][4],
                                         uint32_t xhi, uint32_t xlo,
                                         uint32_t whi, uint32_t wlo,
                                         int lane, int wm, int wn) {
    const int arow = wm * 16 + (lane & 15);
    const int acolo = (lane >> 4) * 8;
    const int brow = wn * 16 + (lane & 7) + ((lane >> 4) & 1) * 8;
    const int bcolo = ((lane >> 3) & 1) * 8;
#pragma unroll 2
    for (int ks = 0; ks < 8; ks++) {
        uint32_t Ah[4], Al[4], Bh[4], Bl[4];
        uint32_t ao = (uint32_t)(arow * PAD + ks * 16 + acolo) * 2;
        uint32_t bo = (uint32_t)(brow * PAD + ks * 16 + bcolo) * 2;
        LDSM4(Ah, xhi + ao);
        LDSM4(Al, xlo + ao);
        LDSM4(Bh, whi + bo);
        LDSM4(Bl, wlo + bo);
#pragma unroll
        for (int tn = 0; tn < 2; tn++) {
            int o = tn * 2;
            MMA16816(acc[tn], Ah, Bh[o], Bh[o + 1]);
            MMA16816(acc[tn], Al, Bh[o], Bh[o + 1]);
            MMA16816(acc[tn], Ah, Bl[o], Bl[o + 1]);
        }
    }
}

__device__ __forceinline__ void stage_gzgh(uint32_t sb, int tile, int t, int buf, int tid) {
    const float* srcz = g_GZ + ((size_t)t * NRP + (size_t)tile * 32) * D;
    const float* srch = g_GH + ((size_t)t * NRP + (size_t)tile * 32) * D;
    for (int i = tid; i < 2048; i += 512) {
        int which = i >> 10, j = i & 1023;
        int row = j >> 5, c = j & 31;
        const float* s = (which ? srch : srcz) + row * 128 + c * 4;
        uint32_t d = sb + GST + buf * GBUF + which * GHALF + row * GROW + c * 16;
        CP_ASYNC16(d, s);
    }
    CP_COMMIT();
}

__global__ void __launch_bounds__(512, 1) step_all(const float* __restrict__ bz,
                                                   const float* __restrict__ bh,
                                                   float* __restrict__ out) {
    extern __shared__ char sm[];
    uint32_t sb = smem_u32(sm);
    int tid = threadIdx.x, lane = tid & 31, wid = tid >> 5;
    int wm = wid & 1, wn = wid >> 1;

    copy_w_pad(sm, 2, tid, SW0_HI, SW0_LO);  // Uz
    copy_w_pad(sm, 4, tid, SW1_HI, SW1_LO);  // Uh

    int cols[2], rowsl[2];
#pragma unroll
    for (int tn = 0; tn < 2; tn++) cols[tn] = wn * 16 + tn * 8 + (lane & 3) * 2;
#pragma unroll
    for (int h2 = 0; h2 < 2; h2++) rowsl[h2] = wm * 16 + (lane >> 2) + h2 * 8;

    float2 bzv[2], bhv[2];
#pragma unroll
    for (int tn = 0; tn < 2; tn++) {
        bzv[tn] = *(const float2*)(bz + cols[tn]);
        bhv[tn] = *(const float2*)(bh + cols[tn]);
    }
    __syncthreads();  // weights ready

    for (int tile = blockIdx.x; tile < NTIL32; tile += gridDim.x) {
        float S[2][4];
#pragma unroll
        for (int tn = 0; tn < 2; tn++)
#pragma unroll
            for (int q = 0; q < 4; q++) S[tn][q] = 0.f;

        stage_gzgh(sb, tile, 0, 0, tid);

        for (int t = 0; t < NT; t++) {
            int buf = t & 1;
            if (t + 1 < NT) {
                stage_gzgh(sb, tile, t + 1, buf ^ 1, tid);
                CP_WAIT1();   // group t complete (t+1 may be pending)
            } else {
                CP_WAIT0();
            }
            __syncthreads();  // staged t visible to all; SX free

            // read GZ/GH fragments from staged smem
            float2 gz[2][2], gh[2][2];
#pragma unroll
            for (int tn = 0; tn < 2; tn++)
#pragma unroll
                for (int h2 = 0; h2 < 2; h2++) {
                    uint32_t off = GST + buf * GBUF + (uint32_t)(rowsl[h2] * GROW + cols[tn] * 4);
                    gz[tn][h2] = *(const float2*)(sm + off);
                    gh[tn][h2] = *(const float2*)(sm + off + GHALF);
                }

            float aZ[2][4], aH[2][4];
#pragma unroll
            for (int tn = 0; tn < 2; tn++)
#pragma unroll
                for (int q = 0; q < 4; q++) { aZ[tn][q] = 0.f; aH[tn][q] = 0.f; }

            if (t > 0) {
#pragma unroll
                for (int tn = 0; tn < 2; tn++)
#pragma unroll
                    for (int h2 = 0; h2 < 2; h2++) {
                        uint32_t h, l;
                        split2(S[tn][h2 * 2], S[tn][h2 * 2 + 1], h, l);
                        uint32_t off = (uint32_t)(rowsl[h2] * PAD + cols[tn]) * 2;
                        *(uint32_t*)(sm + SX_HI + off) = h;
                        *(uint32_t*)(sm + SX_LO + off) = l;
                    }
                __syncthreads();
                gemm_w16(aZ, sb + SX_HI, sb + SX_LO, sb + SW0_HI, sb + SW0_LO, lane, wm, wn);
                gemm_w16(aH, sb + SX_HI, sb + SX_LO, sb + SW1_HI, sb + SW1_LO, lane, wm, wn);
            }

#pragma unroll
            for (int tn = 0; tn < 2; tn++)
#pragma unroll
                for (int h2 = 0; h2 < 2; h2++) {
                    float z0 = 1.f / (1.f + expf(-(gz[tn][h2].x + aZ[tn][h2 * 2]     + bzv[tn].x)));
                    float z1 = 1.f / (1.f + expf(-(gz[tn][h2].y + aZ[tn][h2 * 2 + 1] + bzv[tn].y)));
                    float c0 = tanhf(gh[tn][h2].x + aH[tn][h2 * 2]     + bhv[tn].x);
                    float c1 = tanhf(gh[tn][h2].y + aH[tn][h2 * 2 + 1] + bhv[tn].y);
                    S[tn][h2 * 2]     = (1.f - z0) * S[tn][h2 * 2]     + z0 * c0;
                    S[tn][h2 * 2 + 1] = (1.f - z1) * S[tn][h2 * 2 + 1] + z1 * c1;
                }
            __syncthreads();  // staged buf + SX reads done before reuse
        }

#pragma unroll
        for (int tn = 0; tn < 2; tn++)
#pragma unroll
            for (int h2 = 0; h2 < 2; h2++) {
                int grow = tile * 32 + rowsl[h2];
                *(float2*)(out + (size_t)grow * D + cols[tn]) =
                    make_float2(S[tn][h2 * 2], S[tn][h2 * 2 + 1]);
            }
    }
}

// ---------------------------------------------------------------------------
extern "C" void kernel_launch(void* const* d_in, const int* in_sizes, int n_in,
                              void* d_out, int out_size) {
    const int*   ei       = (const int*)d_in[0];
    const int*   src      = ei;
    const int*   dst      = ei + NE;
    const int*   etype    = (const int*)d_in[1];
    const int*   etime    = (const int*)d_in[2];
    const float* ew       = (const float*)d_in[3];
    const float* node_emb = (const float*)d_in[4];
    const float* rel_emb  = (const float*)d_in[5];
    const float* Wenc     = (const float*)d_in[6];
    const float* Wz       = (const float*)d_in[7];
    const float* Uz       = (const float*)d_in[8];
    const float* Wh       = (const float*)d_in[9];
    const float* Uh       = (const float*)d_in[10];
    const float* bz       = (const float*)d_in[11];
    const float* bh       = (const float*)d_in[12];

    cudaFuncSetAttribute(enc_gates, cudaFuncAttributeMaxDynamicSharedMemorySize, SMEM_ENC);
    cudaFuncSetAttribute(step_all,  cudaFuncAttributeMaxDynamicSharedMemorySize, SMEM_STEP);

    zero_kernel<<<2048, 256>>>();
    prep_weights<<<(5 * 128 * 128 + 255) / 256, 256>>>(Wenc, Wz, Uz, Wh, Uh);
    scatter_kernel<<<(NE * 32 + 255) / 256, 256>>>(src, dst, etype, etime, ew,
                                                   node_emb, rel_emb);

    enc_gates<<<148, 512, SMEM_ENC>>>();
    step_all<<<148, 512, SMEM_STEP>>>(bz, bh, (float*)d_out);
}

// round 8
// speedup vs baseline: 1.9977x; 1.0395x over previous
#include <cuda_runtime.h>
#include <cuda_bf16.h>
#include <cstdint>

#define NN 20000    // nodes
#define D  128      // dim
#define NE 200000   // edges
#define NT 8        // timesteps
#define NRP 20096   // padded rows (157*128)
#define NTIL64 314  // 64-row tiles (NRP/64)
#define NTT (NT * NTIL64)   // 2512 (t,tile) pairs for enc_gates
#define NTIL32 625  // 32-row tiles for step_all (exact: 625*32 = 20000)
#define PAD 136     // bf16 elems per padded smem row (step_all layout)

// ---- static device scratch (no runtime allocation) ----
__device__ float g_agg[(size_t)NT * NRP * D];  // per-time aggregated messages
__device__ uint4 g_Wp[5 * 2 * 128 * 16];       // 5 weights x {hi,lo} x [n][k] bf16 linear
__device__ float g_GZ[(size_t)NT * NRP * D];   // H@Wz (fp32 preact)
__device__ float g_GH[(size_t)NT * NRP * D];   // H@Wh

// ---- enc_gates smem (XOR-swizzled 256B rows) ----
#define EX_HI 0
#define EX_LO 16384
#define EWE_HI 32768
#define EWE_LO 65536
#define EWZ_HI 98304
#define EWZ_LO 131072
#define EWH_HI 163840
#define EWH_LO 196608
#define SMEM_ENC 229376

// ---- step_all smem (padded rows for X/W + GZ/GH staging) ----
#define SX_HI 0
#define SX_LO 8704
#define SW0_HI 17408
#define SW0_LO 52224
#define SW1_HI 87040
#define SW1_LO 121856
#define GST 156672
#define GROW 528              // staged row stride (bytes): 512 + 16 pad
#define GHALF (32 * GROW)     // 16896: one GZ or GH tile
#define GBUF (2 * GHALF)      // 33792: GZ+GH for one t
#define SMEM_STEP (GST + 2 * GBUF)   // 224256

// ---------------------------------------------------------------------------
__device__ __forceinline__ uint32_t smem_u32(const void* p) {
    uint32_t a;
    asm("{ .reg .u64 t; cvta.to.shared.u64 t, %1; cvt.u32.u64 %0, t; }" : "=r"(a) : "l"(p));
    return a;
}

#define CP_ASYNC16(dst, src) \
    asm volatile("cp.async.cg.shared.global [%0], [%1], 16;" :: "r"(dst), "l"(src) : "memory")
#define CP_COMMIT() asm volatile("cp.async.commit_group;" ::: "memory")
#define CP_WAIT0()  asm volatile("cp.async.wait_group 0;" ::: "memory")
#define CP_WAIT1()  asm volatile("cp.async.wait_group 1;" ::: "memory")

#define LDSM4(R, a) \
    asm volatile("ldmatrix.sync.aligned.m8n8.x4.shared.b16 {%0,%1,%2,%3}, [%4];" \
                 : "=r"((R)[0]), "=r"((R)[1]), "=r"((R)[2]), "=r"((R)[3]) : "r"(a))

#define MMA16816(d, a, b0, b1) \
    asm volatile("mma.sync.aligned.m16n8k16.row.col.f32.bf16.bf16.f32 " \
                 "{%0,%1,%2,%3},{%4,%5,%6,%7},{%8,%9},{%0,%1,%2,%3};" \
                 : "+f"((d)[0]), "+f"((d)[1]), "+f"((d)[2]), "+f"((d)[3]) \
                 : "r"((a)[0]), "r"((a)[1]), "r"((a)[2]), "r"((a)[3]), "r"(b0), "r"(b1))

__device__ __forceinline__ void split2(float x, float y, uint32_t& h, uint32_t& l) {
    __nv_bfloat16 hx = __float2bfloat16(x), hy = __float2bfloat16(y);
    float rx = x - __bfloat162float(hx);
    float ry = y - __bfloat162float(hy);
    __nv_bfloat16 lx = __float2bfloat16(rx), ly = __float2bfloat16(ry);
    h = (uint32_t)__bfloat16_as_ushort(hx) | ((uint32_t)__bfloat16_as_ushort(hy) << 16);
    l = (uint32_t)__bfloat16_as_ushort(lx) | ((uint32_t)__bfloat16_as_ushort(ly) << 16);
}

// ---------------------------------------------------------------------------
__global__ void prep_weights(const float* W0, const float* W1, const float* W2,
                             const float* W3, const float* W4) {
    int idx = blockIdx.x * blockDim.x + threadIdx.x;
    if (idx >= 5 * 128 * 128) return;
    int w = idx >> 14, rem = idx & 16383, n = rem >> 7, k = rem & 127;
    const float* Ws = (w == 0) ? W0 : (w == 1) ? W1 : (w == 2) ? W2 : (w == 3) ? W3 : W4;
    float v = Ws[k * 128 + n];
    __nv_bfloat16 hv = __float2bfloat16(v);
    float res = v - __bfloat162float(hv);
    __nv_bfloat16 lv = __float2bfloat16(res);
    unsigned short* base = (unsigned short*)g_Wp;
    base[(size_t)((w * 2 + 0) * 128 + n) * 128 + k] = __bfloat16_as_ushort(hv);
    base[(size_t)((w * 2 + 1) * 128 + n) * 128 + k] = __bfloat16_as_ushort(lv);
}

__global__ void scatter_kernel(const int* __restrict__ src, const int* __restrict__ dst,
                               const int* __restrict__ etype, const int* __restrict__ etime,
                               const float* __restrict__ ew,
                               const float* __restrict__ node_emb,
                               const float* __restrict__ rel_emb) {
    int gid  = blockIdx.x * blockDim.x + threadIdx.x;
    int e    = gid >> 5;
    int lane = gid & 31;
    if (e >= NE) return;
    int t = etime[e];
    if ((unsigned)t >= NT) return;
    int s = src[e], d = dst[e], r = etype[e];
    float w = ew[e];
    float4 a = reinterpret_cast<const float4*>(node_emb + (size_t)s * D)[lane];
    float4 b = reinterpret_cast<const float4*>(rel_emb  + (size_t)r * D)[lane];
    float* o = g_agg + ((size_t)t * NRP + d) * D + lane * 4;
    asm volatile("red.global.add.v4.f32 [%0], {%1,%2,%3,%4};"
                 :: "l"(o), "f"(a.x * b.x * w), "f"(a.y * b.y * w),
                    "f"(a.z * b.z * w), "f"(a.w * b.w * w) : "memory");
}

// ---------------------------------------------------------------------------
// enc_gates: fused H = tanh(agg@Wenc) (smem-only), then GZ/GH in ONE dual
// k-loop sharing the H fragments. 64-row tiles, 512 thr, XOR-swizzle 256B rows.
// ---------------------------------------------------------------------------
__device__ __forceinline__ void copy_w_swz(char* sm_, int w, int tid,
                                           int hi_off, int lo_off) {
    const uint4* s = g_Wp + (size_t)w * 4096;
    for (int i = tid; i < 4096; i += 512) {
        int sp = i >> 11, j = i & 2047, n = j >> 4, c = j & 15;
        uint32_t off = (uint32_t)(n * 256) + (((c ^ (n & 7)) & 15) << 4);
        *(uint4*)(sm_ + (sp ? lo_off : hi_off) + off) = s[i];
    }
}

// single GEMM (encoder): warp grid 2(m) x 8(n), tile 32x16, bf16x3
__device__ __forceinline__ void gemm64sw(float (&acc)[2][2][4],
                                         uint32_t xhi, uint32_t xlo,
                                         uint32_t whi, uint32_t wlo,
                                         int lane, int wm, int wn) {
    int ar = wm * 32 + (lane & 15);
    int ach = lane >> 4;
    int brow = wn * 16 + (lane & 7) + ((lane >> 4) & 1) * 8;
    int bch = (lane >> 3) & 1;
    uint32_t ab0 = (uint32_t)(ar * 256), ab1 = (uint32_t)((ar + 16) * 256);
    int am = ar & 7;
    uint32_t bb = (uint32_t)(brow * 256);
    int bm = brow & 7;
#pragma unroll 2
    for (int ks = 0; ks < 8; ks++) {
        uint32_t Ah[2][4], Al[2][4], Bh[4], Bl[4];
        uint32_t ao = (uint32_t)((((ks * 2 + ach) ^ am) & 15) << 4);
        uint32_t bo = (uint32_t)((((ks * 2 + bch) ^ bm) & 15) << 4);
        LDSM4(Ah[0], xhi + ab0 + ao);
        LDSM4(Al[0], xlo + ab0 + ao);
        LDSM4(Ah[1], xhi + ab1 + ao);
        LDSM4(Al[1], xlo + ab1 + ao);
        LDSM4(Bh, whi + bb + bo);
        LDSM4(Bl, wlo + bb + bo);
#pragma unroll
        for (int tm = 0; tm < 2; tm++)
#pragma unroll
            for (int tn = 0; tn < 2; tn++) {
                int o = tn * 2;
                MMA16816(acc[tm][tn], Ah[tm], Bh[o], Bh[o + 1]);
                MMA16816(acc[tm][tn], Al[tm], Bh[o], Bh[o + 1]);
                MMA16816(acc[tm][tn], Ah[tm], Bl[o], Bl[o + 1]);
            }
    }
}

// dual GEMM (GZ + GH) sharing A fragments: 8 LDSM -> 24 MMA per k-step
__device__ __forceinline__ void gemm64sw_dual(float (&aZ)[2][2][4], float (&aH)[2][2][4],
                                              uint32_t xhi, uint32_t xlo,
                                              uint32_t zhi, uint32_t zlo,
                                              uint32_t hhi, uint32_t hlo,
                                              int lane, int wm, int wn) {
    int ar = wm * 32 + (lane & 15);
    int ach = lane >> 4;
    int brow = wn * 16 + (lane & 7) + ((lane >> 4) & 1) * 8;
    int bch = (lane >> 3) & 1;
    uint32_t ab0 = (uint32_t)(ar * 256), ab1 = (uint32_t)((ar + 16) * 256);
    int am = ar & 7;
    uint32_t bb = (uint32_t)(brow * 256);
    int bm = brow & 7;
#pragma unroll 1
    for (int ks = 0; ks < 8; ks++) {
        uint32_t Ah[2][4], Al[2][4], Bzh[4], Bzl[4], Bhh[4], Bhl[4];
        uint32_t ao = (uint32_t)((((ks * 2 + ach) ^ am) & 15) << 4);
        uint32_t bo = (uint32_t)((((ks * 2 + bch) ^ bm) & 15) << 4);
        LDSM4(Ah[0], xhi + ab0 + ao);
        LDSM4(Al[0], xlo + ab0 + ao);
        LDSM4(Ah[1], xhi + ab1 + ao);
        LDSM4(Al[1], xlo + ab1 + ao);
        LDSM4(Bzh, zhi + bb + bo);
        LDSM4(Bzl, zlo + bb + bo);
        LDSM4(Bhh, hhi + bb + bo);
        LDSM4(Bhl, hlo + bb + bo);
#pragma unroll
        for (int tm = 0; tm < 2; tm++)
#pragma unroll
            for (int tn = 0; tn < 2; tn++) {
                int o = tn * 2;
                MMA16816(aZ[tm][tn], Ah[tm], Bzh[o], Bzh[o + 1]);
                MMA16816(aZ[tm][tn], Al[tm], Bzh[o], Bzh[o + 1]);
                MMA16816(aZ[tm][tn], Ah[tm], Bzl[o], Bzl[o + 1]);
                MMA16816(aH[tm][tn], Ah[tm], Bhh[o], Bhh[o + 1]);
                MMA16816(aH[tm][tn], Al[tm], Bhh[o], Bhh[o + 1]);
                MMA16816(aH[tm][tn], Ah[tm], Bhl[o], Bhl[o + 1]);
            }
    }
}

#define ZERO_ACC224(acc) \
    { _Pragma("unroll") for (int i = 0; i < 2; i++) \
      _Pragma("unroll") for (int j = 0; j < 2; j++) \
      _Pragma("unroll") for (int q = 0; q < 4; q++) (acc)[i][j][q] = 0.f; }

__global__ void __launch_bounds__(512, 1) enc_gates() {
    extern __shared__ char sm[];
    uint32_t sb = smem_u32(sm);
    int tid = threadIdx.x, lane = tid & 31, wid = tid >> 5;
    int wm = wid & 1, wn = wid >> 1;

    copy_w_swz(sm, 0, tid, EWE_HI, EWE_LO);  // Wenc
    copy_w_swz(sm, 1, tid, EWZ_HI, EWZ_LO);  // Wz
    copy_w_swz(sm, 3, tid, EWH_HI, EWH_LO);  // Wh

    int xrow = tid >> 3, xseg = (tid & 7) * 16;
    int xc0 = xseg >> 3;

    float4 pf[4];
    {
        int tt = blockIdx.x;
        int t = tt / NTIL64, tile = tt - t * NTIL64;
        const float4* s = (const float4*)(g_agg + ((size_t)t * NRP + tile * 64 + xrow) * D + xseg);
#pragma unroll
        for (int q = 0; q < 4; q++) pf[q] = s[q];
    }

    for (int tt = blockIdx.x; tt < NTT; tt += gridDim.x) {
        int t = tt / NTIL64, tile = tt - t * NTIL64;

        __syncthreads();  // X free (prev ZH gemm done with H)
#pragma unroll
        for (int g = 0; g < 2; g++) {
            float4 a = pf[g * 2], b = pf[g * 2 + 1];
            uint32_t h0, h1, h2, h3, l0, l1, l2, l3;
            split2(a.x, a.y, h0, l0);
            split2(a.z, a.w, h1, l1);
            split2(b.x, b.y, h2, l2);
            split2(b.z, b.w, h3, l3);
            uint32_t off = (uint32_t)(xrow * 256) + ((((xc0 + g) ^ (xrow & 7)) & 15) << 4);
            *(uint4*)(sm + EX_HI + off) = make_uint4(h0, h1, h2, h3);
            *(uint4*)(sm + EX_LO + off) = make_uint4(l0, l1, l2, l3);
        }
        __syncthreads();  // X ready

        // encoder GEMM
        float acc[2][2][4];
        ZERO_ACC224(acc);
        gemm64sw(acc, sb + EX_HI, sb + EX_LO, sb + EWE_HI, sb + EWE_LO, lane, wm, wn);
        __syncthreads();  // all warps done reading agg X

        // tanh + split H back into X buffers
#pragma unroll
        for (int tm = 0; tm < 2; tm++)
#pragma unroll
            for (int tn = 0; tn < 2; tn++) {
                int c = wn * 16 + tn * 8 + (lane & 3) * 2;
#pragma unroll
                for (int h2i = 0; h2i < 2; h2i++) {
                    int r = wm * 32 + tm * 16 + (lane >> 2) + h2i * 8;
                    uint32_t h, l;
                    split2(tanhf(acc[tm][tn][h2i * 2]), tanhf(acc[tm][tn][h2i * 2 + 1]), h, l);
                    uint32_t off = (uint32_t)(r * 256) + ((((c >> 3) ^ (r & 7)) & 15) << 4)
                                 + (uint32_t)((c & 7) * 2);
                    *(uint32_t*)(sm + EX_HI + off) = h;
                    *(uint32_t*)(sm + EX_LO + off) = l;
                }
            }
        __syncthreads();  // H ready

        // prefetch next tile's agg (hides under dual gemm)
        if (tt + (int)gridDim.x < NTT) {
            int nt2 = tt + gridDim.x;
            int t2 = nt2 / NTIL64, tile2 = nt2 - t2 * NTIL64;
            const float4* s = (const float4*)(g_agg + ((size_t)t2 * NRP + tile2 * 64 + xrow) * D + xseg);
#pragma unroll
            for (int q = 0; q < 4; q++) pf[q] = s[q];
        }

        // dual GEMM: GZ and GH share the H fragment loads
        float accZ[2][2][4], accH[2][2][4];
        ZERO_ACC224(accZ);
        ZERO_ACC224(accH);
        gemm64sw_dual(accZ, accH, sb + EX_HI, sb + EX_LO,
                      sb + EWZ_HI, sb + EWZ_LO, sb + EWH_HI, sb + EWH_LO, lane, wm, wn);

        size_t base = (size_t)t * NRP + (size_t)tile * 64;
#pragma unroll
        for (int tm = 0; tm < 2; tm++)
#pragma unroll
            for (int tn = 0; tn < 2; tn++) {
                int c = wn * 16 + tn * 8 + (lane & 3) * 2;
#pragma unroll
                for (int h2i = 0; h2i < 2; h2i++) {
                    int r = wm * 32 + tm * 16 + (lane >> 2) + h2i * 8;
                    *(float2*)(g_GZ + (base + r) * D + c) =
                        make_float2(accZ[tm][tn][h2i * 2], accZ[tm][tn][h2i * 2 + 1]);
                    *(float2*)(g_GH + (base + r) * D + c) =
                        make_float2(accH[tm][tn][h2i * 2], accH[tm][tn][h2i * 2 + 1]);
                }
            }
    }
}

// ---------------------------------------------------------------------------
// step_all: all timesteps, state in registers; Uz/Uh resident; dual k-loop
// shares state fragments; GZ/GH double-buffered via cp.async.
// ---------------------------------------------------------------------------
__device__ __forceinline__ void copy_w_pad(char* sm_, int w, int tid,
                                           int hi_off, int lo_off) {
    const uint4* s = g_Wp + (size_t)w * 4096;
    for (int i = tid; i < 4096; i += 512) {
        int sp = i >> 11, j = i & 2047, n = j >> 4, kk = j & 15;
        *(uint4*)(sm_ + (sp ? lo_off : hi_off) + (uint32_t)(n * PAD + kk * 8) * 2) = s[i];
    }
}

// dual 16x16 GEMM sharing A: 6 LDSM -> 12 MMA per k-step
__device__ __forceinline__ void gemm_w16_dual(float (&aZ)[2][4], float (&aH)[2][4],
                                              uint32_t xhi, uint32_t xlo,
                                              uint32_t zhi, uint32_t zlo,
                                              uint32_t hhi, uint32_t hlo,
                                              int lane, int wm, int wn) {
    const int arow = wm * 16 + (lane & 15);
    const int acolo = (lane >> 4) * 8;
    const int brow = wn * 16 + (lane & 7) + ((lane >> 4) & 1) * 8;
    const int bcolo = ((lane >> 3) & 1) * 8;
#pragma unroll 2
    for (int ks = 0; ks < 8; ks++) {
        uint32_t Ah[4], Al[4], Bzh[4], Bzl[4], Bhh[4], Bhl[4];
        uint32_t ao = (uint32_t)(arow * PAD + ks * 16 + acolo) * 2;
        uint32_t bo = (uint32_t)(brow * PAD + ks * 16 + bcolo) * 2;
        LDSM4(Ah, xhi + ao);
        LDSM4(Al, xlo + ao);
        LDSM4(Bzh, zhi + bo);
        LDSM4(Bzl, zlo + bo);
        LDSM4(Bhh, hhi + bo);
        LDSM4(Bhl, hlo + bo);
#pragma unroll
        for (int tn = 0; tn < 2; tn++) {
            int o = tn * 2;
            MMA16816(aZ[tn], Ah, Bzh[o], Bzh[o + 1]);
            MMA16816(aZ[tn], Al, Bzh[o], Bzh[o + 1]);
            MMA16816(aZ[tn], Ah, Bzl[o], Bzl[o + 1]);
            MMA16816(aH[tn], Ah, Bhh[o], Bhh[o + 1]);
            MMA16816(aH[tn], Al, Bhh[o], Bhh[o + 1]);
            MMA16816(aH[tn], Ah, Bhl[o], Bhl[o + 1]);
        }
    }
}

__device__ __forceinline__ void stage_gzgh(uint32_t sb, int tile, int t, int buf, int tid) {
    const float* srcz = g_GZ + ((size_t)t * NRP + (size_t)tile * 32) * D;
    const float* srch = g_GH + ((size_t)t * NRP + (size_t)tile * 32) * D;
    for (int i = tid; i < 2048; i += 512) {
        int which = i >> 10, j = i & 1023;
        int row = j >> 5, c = j & 31;
        const float* s = (which ? srch : srcz) + row * 128 + c * 4;
        uint32_t d = sb + GST + buf * GBUF + which * GHALF + row * GROW + c * 16;
        CP_ASYNC16(d, s);
    }
    CP_COMMIT();
}

__global__ void __launch_bounds__(512, 1) step_all(const float* __restrict__ bz,
                                                   const float* __restrict__ bh,
                                                   float* __restrict__ out) {
    extern __shared__ char sm[];
    uint32_t sb = smem_u32(sm);
    int tid = threadIdx.x, lane = tid & 31, wid = tid >> 5;
    int wm = wid & 1, wn = wid >> 1;

    copy_w_pad(sm, 2, tid, SW0_HI, SW0_LO);  // Uz
    copy_w_pad(sm, 4, tid, SW1_HI, SW1_LO);  // Uh

    int cols[2], rowsl[2];
#pragma unroll
    for (int tn = 0; tn < 2; tn++) cols[tn] = wn * 16 + tn * 8 + (lane & 3) * 2;
#pragma unroll
    for (int h2 = 0; h2 < 2; h2++) rowsl[h2] = wm * 16 + (lane >> 2) + h2 * 8;

    float2 bzv[2], bhv[2];
#pragma unroll
    for (int tn = 0; tn < 2; tn++) {
        bzv[tn] = *(const float2*)(bz + cols[tn]);
        bhv[tn] = *(const float2*)(bh + cols[tn]);
    }
    __syncthreads();  // weights ready

    for (int tile = blockIdx.x; tile < NTIL32; tile += gridDim.x) {
        float S[2][4];
#pragma unroll
        for (int tn = 0; tn < 2; tn++)
#pragma unroll
            for (int q = 0; q < 4; q++) S[tn][q] = 0.f;

        stage_gzgh(sb, tile, 0, 0, tid);

        for (int t = 0; t < NT; t++) {
            int buf = t & 1;
            if (t + 1 < NT) {
                stage_gzgh(sb, tile, t + 1, buf ^ 1, tid);
                CP_WAIT1();
            } else {
                CP_WAIT0();
            }
            __syncthreads();  // staged t visible; SX free

            float2 gz[2][2], gh[2][2];
#pragma unroll
            for (int tn = 0; tn < 2; tn++)
#pragma unroll
                for (int h2 = 0; h2 < 2; h2++) {
                    uint32_t off = GST + buf * GBUF + (uint32_t)(rowsl[h2] * GROW + cols[tn] * 4);
                    gz[tn][h2] = *(const float2*)(sm + off);
                    gh[tn][h2] = *(const float2*)(sm + off + GHALF);
                }

            float aZ[2][4], aH[2][4];
#pragma unroll
            for (int tn = 0; tn < 2; tn++)
#pragma unroll
                for (int q = 0; q < 4; q++) { aZ[tn][q] = 0.f; aH[tn][q] = 0.f; }

            if (t > 0) {
#pragma unroll
                for (int tn = 0; tn < 2; tn++)
#pragma unroll
                    for (int h2 = 0; h2 < 2; h2++) {
                        uint32_t h, l;
                        split2(S[tn][h2 * 2], S[tn][h2 * 2 + 1], h, l);
                        uint32_t off = (uint32_t)(rowsl[h2] * PAD + cols[tn]) * 2;
                        *(uint32_t*)(sm + SX_HI + off) = h;
                        *(uint32_t*)(sm + SX_LO + off) = l;
                    }
                __syncthreads();
                gemm_w16_dual(aZ, aH, sb + SX_HI, sb + SX_LO,
                              sb + SW0_HI, sb + SW0_LO, sb + SW1_HI, sb + SW1_LO,
                              lane, wm, wn);
            }

#pragma unroll
            for (int tn = 0; tn < 2; tn++)
#pragma unroll
                for (int h2 = 0; h2 < 2; h2++) {
                    float z0 = 1.f / (1.f + expf(-(gz[tn][h2].x + aZ[tn][h2 * 2]     + bzv[tn].x)));
                    float z1 = 1.f / (1.f + expf(-(gz[tn][h2].y + aZ[tn][h2 * 2 + 1] + bzv[tn].y)));
                    float c0 = tanhf(gh[tn][h2].x + aH[tn][h2 * 2]     + bhv[tn].x);
                    float c1 = tanhf(gh[tn][h2].y + aH[tn][h2 * 2 + 1] + bhv[tn].y);
                    S[tn][h2 * 2]     = (1.f - z0) * S[tn][h2 * 2]     + z0 * c0;
                    S[tn][h2 * 2 + 1] = (1.f - z1) * S[tn][h2 * 2 + 1] + z1 * c1;
                }
            __syncthreads();  // staged buf + SX reads done before reuse
        }

#pragma unroll
        for (int tn = 0; tn < 2; tn++)
#pragma unroll
            for (int h2 = 0; h2 < 2; h2++) {
                int grow = tile * 32 + rowsl[h2];
                *(float2*)(out + (size_t)grow * D + cols[tn]) =
                    make_float2(S[tn][h2 * 2], S[tn][h2 * 2 + 1]);
            }
    }
}

// ---------------------------------------------------------------------------
extern "C" void kernel_launch(void* const* d_in, const int* in_sizes, int n_in,
                              void* d_out, int out_size) {
    const int*   ei       = (const int*)d_in[0];
    const int*   src      = ei;
    const int*   dst      = ei + NE;
    const int*   etype    = (const int*)d_in[1];
    const int*   etime    = (const int*)d_in[2];
    const float* ew       = (const float*)d_in[3];
    const float* node_emb = (const float*)d_in[4];
    const float* rel_emb  = (const float*)d_in[5];
    const float* Wenc     = (const float*)d_in[6];
    const float* Wz       = (const float*)d_in[7];
    const float* Uz       = (const float*)d_in[8];
    const float* Wh       = (const float*)d_in[9];
    const float* Uh       = (const float*)d_in[10];
    const float* bz       = (const float*)d_in[11];
    const float* bh       = (const float*)d_in[12];

    cudaFuncSetAttribute(enc_gates, cudaFuncAttributeMaxDynamicSharedMemorySize, SMEM_ENC);
    cudaFuncSetAttribute(step_all,  cudaFuncAttributeMaxDynamicSharedMemorySize, SMEM_STEP);

    void* aggp = nullptr;
    cudaGetSymbolAddress(&aggp, g_agg);
    cudaMemsetAsync(aggp, 0, (size_t)NT * NRP * D * sizeof(float), 0);

    prep_weights<<<(5 * 128 * 128 + 255) / 256, 256>>>(Wenc, Wz, Uz, Wh, Uh);
    scatter_kernel<<<(NE * 32 + 255) / 256, 256>>>(src, dst, etype, etime, ew,
                                                   node_emb, rel_emb);

    enc_gates<<<148, 512, SMEM_ENC>>>();
    step_all<<<148, 512, SMEM_STEP>>>(bz, bh, (float*)d_out);
}

// round 10
// speedup vs baseline: 1.9998x; 1.0011x over previous
#include <cuda_runtime.h>
#include <cuda_bf16.h>
#include <cstdint>

#define NN 20000    // nodes
#define D  128      // dim
#define NE 200000   // edges
#define NT 8        // timesteps
#define NRP 20096   // padded rows (157*128)
#define NTIL64 314  // 64-row tiles (NRP/64)
#define NTT (NT * NTIL64)   // 2512 (t,tile) pairs for enc_gates
#define NTIL32 625  // 32-row tiles for step_all (exact: 625*32 = 20000)
#define PAD 136     // bf16 elems per padded smem row (step_all layout)

// ---- static device scratch (no runtime allocation) ----
__device__ float g_agg[(size_t)NT * NRP * D];  // per-time aggregated messages
__device__ uint4 g_Wp[5 * 2 * 128 * 16];       // 5 weights x {hi,lo} x [n][k] bf16 linear
__device__ float g_GZ[(size_t)NT * NRP * D];   // H@Wz (fp32 preact)
__device__ float g_GH[(size_t)NT * NRP * D];   // H@Wh

// ---- enc_gates smem (XOR-swizzled 256B rows) ----
#define EX_HI 0
#define EX_LO 16384
#define EWE_HI 32768
#define EWE_LO 65536
#define EWZ_HI 98304
#define EWZ_LO 131072
#define EWH_HI 163840
#define EWH_LO 196608
#define SMEM_ENC 229376

// ---- step_all smem: Uz + Uh (padded rows) + per-group SX buffers ----
#define SW0_HI 0
#define SW0_LO 34816
#define SW1_HI 69632
#define SW1_LO 104448
#define SXBASE 139264
#define SXG 17408            // per-group SX size (hi 8704 + lo 8704)
#define SMEM_STEP (SXBASE + 2 * SXG)   // 174080

// ---------------------------------------------------------------------------
__device__ __forceinline__ uint32_t smem_u32(const void* p) {
    uint32_t a;
    asm("{ .reg .u64 t; cvta.to.shared.u64 t, %1; cvt.u32.u64 %0, t; }" : "=r"(a) : "l"(p));
    return a;
}

#define LDSM4(R, a) \
    asm volatile("ldmatrix.sync.aligned.m8n8.x4.shared.b16 {%0,%1,%2,%3}, [%4];" \
                 : "=r"((R)[0]), "=r"((R)[1]), "=r"((R)[2]), "=r"((R)[3]) : "r"(a))

#define MMA16816(d, a, b0, b1) \
    asm volatile("mma.sync.aligned.m16n8k16.row.col.f32.bf16.bf16.f32 " \
                 "{%0,%1,%2,%3},{%4,%5,%6,%7},{%8,%9},{%0,%1,%2,%3};" \
                 : "+f"((d)[0]), "+f"((d)[1]), "+f"((d)[2]), "+f"((d)[3]) \
                 : "r"((a)[0]), "r"((a)[1]), "r"((a)[2]), "r"((a)[3]), "r"(b0), "r"(b1))

#define BARH(id) asm volatile("bar.sync %0, 128;" :: "r"(id) : "memory")

__device__ __forceinline__ void split2(float x, float y, uint32_t& h, uint32_t& l) {
    __nv_bfloat16 hx = __float2bfloat16(x), hy = __float2bfloat16(y);
    float rx = x - __bfloat162float(hx);
    float ry = y - __bfloat162float(hy);
    __nv_bfloat16 lx = __float2bfloat16(rx), ly = __float2bfloat16(ry);
    h = (uint32_t)__bfloat16_as_ushort(hx) | ((uint32_t)__bfloat16_as_ushort(hy) << 16);
    l = (uint32_t)__bfloat16_as_ushort(lx) | ((uint32_t)__bfloat16_as_ushort(ly) << 16);
}

// ---------------------------------------------------------------------------
__global__ void prep_weights(const float* W0, const float* W1, const float* W2,
                             const float* W3, const float* W4) {
    int idx = blockIdx.x * blockDim.x + threadIdx.x;
    if (idx >= 5 * 128 * 128) return;
    int w = idx >> 14, rem = idx & 16383, n = rem >> 7, k = rem & 127;
    const float* Ws = (w == 0) ? W0 : (w == 1) ? W1 : (w == 2) ? W2 : (w == 3) ? W3 : W4;
    float v = Ws[k * 128 + n];
    __nv_bfloat16 hv = __float2bfloat16(v);
    float res = v - __bfloat162float(hv);
    __nv_bfloat16 lv = __float2bfloat16(res);
    unsigned short* base = (unsigned short*)g_Wp;
    base[(size_t)((w * 2 + 0) * 128 + n) * 128 + k] = __bfloat16_as_ushort(hv);
    base[(size_t)((w * 2 + 1) * 128 + n) * 128 + k] = __bfloat16_as_ushort(lv);
}

__global__ void scatter_kernel(const int* __restrict__ src, const int* __restrict__ dst,
                               const int* __restrict__ etype, const int* __restrict__ etime,
                               const float* __restrict__ ew,
                               const float* __restrict__ node_emb,
                               const float* __restrict__ rel_emb) {
    int gid  = blockIdx.x * blockDim.x + threadIdx.x;
    int e    = gid >> 5;
    int lane = gid & 31;
    if (e >= NE) return;
    int t = etime[e];
    if ((unsigned)t >= NT) return;
    int s = src[e], d = dst[e], r = etype[e];
    float w = ew[e];
    float4 a = reinterpret_cast<const float4*>(node_emb + (size_t)s * D)[lane];
    float4 b = reinterpret_cast<const float4*>(rel_emb  + (size_t)r * D)[lane];
    float* o = g_agg + ((size_t)t * NRP + d) * D + lane * 4;
    asm volatile("red.global.add.v4.f32 [%0], {%1,%2,%3,%4};"
                 :: "l"(o), "f"(a.x * b.x * w), "f"(a.y * b.y * w),
                    "f"(a.z * b.z * w), "f"(a.w * b.w * w) : "memory");
}

// ---------------------------------------------------------------------------
// enc_gates (unchanged from R8): fused H = tanh(agg@Wenc) smem-only, then
// dual GZ/GH GEMM sharing H fragments. 64-row tiles, 512 thr.
// ---------------------------------------------------------------------------
__device__ __forceinline__ void copy_w_swz(char* sm_, int w, int tid,
                                           int hi_off, int lo_off) {
    const uint4* s = g_Wp + (size_t)w * 4096;
    for (int i = tid; i < 4096; i += 512) {
        int sp = i >> 11, j = i & 2047, n = j >> 4, c = j & 15;
        uint32_t off = (uint32_t)(n * 256) + (((c ^ (n & 7)) & 15) << 4);
        *(uint4*)(sm_ + (sp ? lo_off : hi_off) + off) = s[i];
    }
}

__device__ __forceinline__ void gemm64sw(float (&acc)[2][2][4],
                                         uint32_t xhi, uint32_t xlo,
                                         uint32_t whi, uint32_t wlo,
                                         int lane, int wm, int wn) {
    int ar = wm * 32 + (lane & 15);
    int ach = lane >> 4;
    int brow = wn * 16 + (lane & 7) + ((lane >> 4) & 1) * 8;
    int bch = (lane >> 3) & 1;
    uint32_t ab0 = (uint32_t)(ar * 256), ab1 = (uint32_t)((ar + 16) * 256);
    int am = ar & 7;
    uint32_t bb = (uint32_t)(brow * 256);
    int bm = brow & 7;
#pragma unroll 2
    for (int ks = 0; ks < 8; ks++) {
        uint32_t Ah[2][4], Al[2][4], Bh[4], Bl[4];
        uint32_t ao = (uint32_t)((((ks * 2 + ach) ^ am) & 15) << 4);
        uint32_t bo = (uint32_t)((((ks * 2 + bch) ^ bm) & 15) << 4);
        LDSM4(Ah[0], xhi + ab0 + ao);
        LDSM4(Al[0], xlo + ab0 + ao);
        LDSM4(Ah[1], xhi + ab1 + ao);
        LDSM4(Al[1], xlo + ab1 + ao);
        LDSM4(Bh, whi + bb + bo);
        LDSM4(Bl, wlo + bb + bo);
#pragma unroll
        for (int tm = 0; tm < 2; tm++)
#pragma unroll
            for (int tn = 0; tn < 2; tn++) {
                int o = tn * 2;
                MMA16816(acc[tm][tn], Ah[tm], Bh[o], Bh[o + 1]);
                MMA16816(acc[tm][tn], Al[tm], Bh[o], Bh[o + 1]);
                MMA16816(acc[tm][tn], Ah[tm], Bl[o], Bl[o + 1]);
            }
    }
}

__device__ __forceinline__ void gemm64sw_dual(float (&aZ)[2][2][4], float (&aH)[2][2][4],
                                              uint32_t xhi, uint32_t xlo,
                                              uint32_t zhi, uint32_t zlo,
                                              uint32_t hhi, uint32_t hlo,
                                              int lane, int wm, int wn) {
    int ar = wm * 32 + (lane & 15);
    int ach = lane >> 4;
    int brow = wn * 16 + (lane & 7) + ((lane >> 4) & 1) * 8;
    int bch = (lane >> 3) & 1;
    uint32_t ab0 = (uint32_t)(ar * 256), ab1 = (uint32_t)((ar + 16) * 256);
    int am = ar & 7;
    uint32_t bb = (uint32_t)(brow * 256);
    int bm = brow & 7;
#pragma unroll 1
    for (int ks = 0; ks < 8; ks++) {
        uint32_t Ah[2][4], Al[2][4], Bzh[4], Bzl[4], Bhh[4], Bhl[4];
        uint32_t ao = (uint32_t)((((ks * 2 + ach) ^ am) & 15) << 4);
        uint32_t bo = (uint32_t)((((ks * 2 + bch) ^ bm) & 15) << 4);
        LDSM4(Ah[0], xhi + ab0 + ao);
        LDSM4(Al[0], xlo + ab0 + ao);
        LDSM4(Ah[1], xhi + ab1 + ao);
        LDSM4(Al[1], xlo + ab1 + ao);
        LDSM4(Bzh, zhi + bb + bo);
        LDSM4(Bzl, zlo + bb + bo);
        LDSM4(Bhh, hhi + bb + bo);
        LDSM4(Bhl, hlo + bb + bo);
#pragma unroll
        for (int tm = 0; tm < 2; tm++)
#pragma unroll
            for (int tn = 0; tn < 2; tn++) {
                int o = tn * 2;
                MMA16816(aZ[tm][tn], Ah[tm], Bzh[o], Bzh[o + 1]);
                MMA16816(aZ[tm][tn], Al[tm], Bzh[o], Bzh[o + 1]);
                MMA16816(aZ[tm][tn], Ah[tm], Bzl[o], Bzl[o + 1]);
                MMA16816(aH[tm][tn], Ah[tm], Bhh[o], Bhh[o + 1]);
                MMA16816(aH[tm][tn], Al[tm], Bhh[o], Bhh[o + 1]);
                MMA16816(aH[tm][tn], Ah[tm], Bhl[o], Bhl[o + 1]);
            }
    }
}

#define ZERO_ACC224(acc) \
    { _Pragma("unroll") for (int i = 0; i < 2; i++) \
      _Pragma("unroll") for (int j = 0; j < 2; j++) \
      _Pragma("unroll") for (int q = 0; q < 4; q++) (acc)[i][j][q] = 0.f; }

__global__ void __launch_bounds__(512, 1) enc_gates() {
    extern __shared__ char sm[];
    uint32_t sb = smem_u32(sm);
    int tid = threadIdx.x, lane = tid & 31, wid = tid >> 5;
    int wm = wid & 1, wn = wid >> 1;

    copy_w_swz(sm, 0, tid, EWE_HI, EWE_LO);
    copy_w_swz(sm, 1, tid, EWZ_HI, EWZ_LO);
    copy_w_swz(sm, 3, tid, EWH_HI, EWH_LO);

    int xrow = tid >> 3, xseg = (tid & 7) * 16;
    int xc0 = xseg >> 3;

    float4 pf[4];
    {
        int tt = blockIdx.x;
        int t = tt / NTIL64, tile = tt - t * NTIL64;
        const float4* s = (const float4*)(g_agg + ((size_t)t * NRP + tile * 64 + xrow) * D + xseg);
#pragma unroll
        for (int q = 0; q < 4; q++) pf[q] = s[q];
    }

    for (int tt = blockIdx.x; tt < NTT; tt += gridDim.x) {
        int t = tt / NTIL64, tile = tt - t * NTIL64;

        __syncthreads();
#pragma unroll
        for (int g = 0; g < 2; g++) {
            float4 a = pf[g * 2], b = pf[g * 2 + 1];
            uint32_t h0, h1, h2, h3, l0, l1, l2, l3;
            split2(a.x, a.y, h0, l0);
            split2(a.z, a.w, h1, l1);
            split2(b.x, b.y, h2, l2);
            split2(b.z, b.w, h3, l3);
            uint32_t off = (uint32_t)(xrow * 256) + ((((xc0 + g) ^ (xrow & 7)) & 15) << 4);
            *(uint4*)(sm + EX_HI + off) = make_uint4(h0, h1, h2, h3);
            *(uint4*)(sm + EX_LO + off) = make_uint4(l0, l1, l2, l3);
        }
        __syncthreads();

        float acc[2][2][4];
        ZERO_ACC224(acc);
        gemm64sw(acc, sb + EX_HI, sb + EX_LO, sb + EWE_HI, sb + EWE_LO, lane, wm, wn);
        __syncthreads();

#pragma unroll
        for (int tm = 0; tm < 2; tm++)
#pragma unroll
            for (int tn = 0; tn < 2; tn++) {
                int c = wn * 16 + tn * 8 + (lane & 3) * 2;
#pragma unroll
                for (int h2i = 0; h2i < 2; h2i++) {
                    int r = wm * 32 + tm * 16 + (lane >> 2) + h2i * 8;
                    uint32_t h, l;
                    split2(tanhf(acc[tm][tn][h2i * 2]), tanhf(acc[tm][tn][h2i * 2 + 1]), h, l);
                    uint32_t off = (uint32_t)(r * 256) + ((((c >> 3) ^ (r & 7)) & 15) << 4)
                                 + (uint32_t)((c & 7) * 2);
                    *(uint32_t*)(sm + EX_HI + off) = h;
                    *(uint32_t*)(sm + EX_LO + off) = l;
                }
            }
        __syncthreads();

        if (tt + (int)gridDim.x < NTT) {
            int nt2 = tt + gridDim.x;
            int t2 = nt2 / NTIL64, tile2 = nt2 - t2 * NTIL64;
            const float4* s = (const float4*)(g_agg + ((size_t)t2 * NRP + tile2 * 64 + xrow) * D + xseg);
#pragma unroll
            for (int q = 0; q < 4; q++) pf[q] = s[q];
        }

        float accZ[2][2][4], accH[2][2][4];
        ZERO_ACC224(accZ);
        ZERO_ACC224(accH);
        gemm64sw_dual(accZ, accH, sb + EX_HI, sb + EX_LO,
                      sb + EWZ_HI, sb + EWZ_LO, sb + EWH_HI, sb + EWH_LO, lane, wm, wn);

        size_t base = (size_t)t * NRP + (size_t)tile * 64;
#pragma unroll
        for (int tm = 0; tm < 2; tm++)
#pragma unroll
            for (int tn = 0; tn < 2; tn++) {
                int c = wn * 16 + tn * 8 + (lane & 3) * 2;
#pragma unroll
                for (int h2i = 0; h2i < 2; h2i++) {
                    int r = wm * 32 + tm * 16 + (lane >> 2) + h2i * 8;
                    *(float2*)(g_GZ + (base + r) * D + c) =
                        make_float2(accZ[tm][tn][h2i * 2], accZ[tm][tn][h2i * 2 + 1]);
                    *(float2*)(g_GH + (base + r) * D + c) =
                        make_float2(accH[tm][tn][h2i * 2], accH[tm][tn][h2i * 2 + 1]);
                }
            }
    }
}

// ---------------------------------------------------------------------------
// step_all: 2 groups/CTA x 2 wm-halves = 4 independent sync domains (named
// bar.sync, 128 thr). Group owns a 32-row tile stream; warp tile 16m x 32n.
// State in registers across t; gz/gh loaded directly (early-issued).
// ---------------------------------------------------------------------------
__device__ __forceinline__ void copy_w_pad(char* sm_, int w, int tid,
                                           int hi_off, int lo_off) {
    const uint4* s = g_Wp + (size_t)w * 4096;
    for (int i = tid; i < 4096; i += 512) {
        int sp = i >> 11, j = i & 2047, n = j >> 4, kk = j & 15;
        *(uint4*)(sm_ + (sp ? lo_off : hi_off) + (uint32_t)(n * PAD + kk * 8) * 2) = s[i];
    }
}

// dual 16m x 32n GEMM (shares A): per ks 10 LDSM -> 24 MMA
__device__ __forceinline__ void gemm_step_dual(float (&aZ)[4][4], float (&aH)[4][4],
                                               uint32_t xhi, uint32_t xlo,
                                               uint32_t zhi, uint32_t zlo,
                                               uint32_t hhi, uint32_t hlo,
                                               int lane, int wm, int wn) {
    const int arow = wm * 16 + (lane & 15);
    const int acolo = (lane >> 4) * 8;
    const int brow = wn * 32 + (lane & 7) + ((lane >> 4) & 1) * 8;
    const int bcolo = ((lane >> 3) & 1) * 8;
    const uint32_t bstep = (uint32_t)(16 * PAD) * 2;   // +16 n-rows
#pragma unroll 1
    for (int ks = 0; ks < 8; ks++) {
        uint32_t Ah[4], Al[4], Bzh[8], Bzl[8], Bhh[8], Bhl[8];
        uint32_t ao = (uint32_t)(arow * PAD + ks * 16 + acolo) * 2;
        uint32_t bo = (uint32_t)(brow * PAD + ks * 16 + bcolo) * 2;
        LDSM4(Ah, xhi + ao);
        LDSM4(Al, xlo + ao);
        LDSM4(Bzh, zhi + bo);
        LDSM4(Bzh + 4, zhi + bo + bstep);
        LDSM4(Bzl, zlo + bo);
        LDSM4(Bzl + 4, zlo + bo + bstep);
        LDSM4(Bhh, hhi + bo);
        LDSM4(Bhh + 4, hhi + bo + bstep);
        LDSM4(Bhl, hlo + bo);
        LDSM4(Bhl + 4, hlo + bo + bstep);
#pragma unroll
        for (int tn = 0; tn < 4; tn++) {
            int o = tn * 2;
            MMA16816(aZ[tn], Ah, Bzh[o], Bzh[o + 1]);
            MMA16816(aZ[tn], Al, Bzh[o], Bzh[o + 1]);
            MMA16816(aZ[tn], Ah, Bzl[o], Bzl[o + 1]);
            MMA16816(aH[tn], Ah, Bhh[o], Bhh[o + 1]);
            MMA16816(aH[tn], Al, Bhh[o], Bhh[o + 1]);
            MMA16816(aH[tn], Ah, Bhl[o], Bhl[o + 1]);
        }
    }
}

__global__ void __launch_bounds__(512, 1) step_all(const float* __restrict__ bz,
                                                   const float* __restrict__ bh,
                                                   float* __restrict__ out) {
    extern __shared__ char sm[];
    uint32_t sb = smem_u32(sm);
    int tid = threadIdx.x, lane = tid & 31, wid = tid >> 5;
    int grp = wid >> 3;            // 0,1: independent tile streams
    int lw = wid & 7;              // warp within group
    int wm = lw & 1, wn = lw >> 1; // 2(m) x 4(n) warp grid, 16x32 tiles
    int barid = 1 + grp * 2 + wm;  // 4 sync domains of 128 threads

    copy_w_pad(sm, 2, tid, SW0_HI, SW0_LO);  // Uz
    copy_w_pad(sm, 4, tid, SW1_HI, SW1_LO);  // Uh

    uint32_t sxhi = sb + SXBASE + grp * SXG;
    uint32_t sxlo = sxhi + 8704;

    int cols[4];
#pragma unroll
    for (int tn = 0; tn < 4; tn++) cols[tn] = wn * 32 + tn * 8 + (lane & 3) * 2;
    int rowsl[2];
#pragma unroll
    for (int h2 = 0; h2 < 2; h2++) rowsl[h2] = wm * 16 + (lane >> 2) + h2 * 8;

    float2 bzv[4], bhv[4];
#pragma unroll
    for (int tn = 0; tn < 4; tn++) {
        bzv[tn] = *(const float2*)(bz + cols[tn]);
        bhv[tn] = *(const float2*)(bh + cols[tn]);
    }
    __syncthreads();  // weights ready (only full-CTA barrier)

    for (int tile = blockIdx.x * 2 + grp; tile < NTIL32; tile += 296) {
        float S[4][4];
#pragma unroll
        for (int tn = 0; tn < 4; tn++)
#pragma unroll
            for (int q = 0; q < 4; q++) S[tn][q] = 0.f;

        for (int t = 0; t < NT; t++) {
            // early-issue gz/gh loads (latency hides under split+gemm)
            size_t base = (size_t)t * NRP + (size_t)tile * 32;
            float2 gz[4][2], gh[4][2];
#pragma unroll
            for (int tn = 0; tn < 4; tn++)
#pragma unroll
                for (int h2 = 0; h2 < 2; h2++) {
                    size_t idx = (base + rowsl[h2]) * D + cols[tn];
                    gz[tn][h2] = *(const float2*)(g_GZ + idx);
                    gh[tn][h2] = *(const float2*)(g_GH + idx);
                }

            float aZ[4][4], aH[4][4];
#pragma unroll
            for (int tn = 0; tn < 4; tn++)
#pragma unroll
                for (int q = 0; q < 4; q++) { aZ[tn][q] = 0.f; aH[tn][q] = 0.f; }

            if (t > 0) {
                // write state splits into this half's SX rows
#pragma unroll
                for (int tn = 0; tn < 4; tn++)
#pragma unroll
                    for (int h2 = 0; h2 < 2; h2++) {
                        uint32_t h, l;
                        split2(S[tn][h2 * 2], S[tn][h2 * 2 + 1], h, l);
                        uint32_t off = (uint32_t)(rowsl[h2] * PAD + cols[tn]) * 2;
                        *(uint32_t*)(sm + SXBASE + grp * SXG + off) = h;
                        *(uint32_t*)(sm + SXBASE + grp * SXG + 8704 + off) = l;
                    }
                BARH(barid);  // half's 16 state rows visible to its 4 warps
                gemm_step_dual(aZ, aH, sxhi, sxlo,
                               sb + SW0_HI, sb + SW0_LO, sb + SW1_HI, sb + SW1_LO,
                               lane, wm, wn);
            }

#pragma unroll
            for (int tn = 0; tn < 4; tn++)
#pragma unroll
                for (int h2 = 0; h2 < 2; h2++) {
                    float z0 = 1.f / (1.f + expf(-(gz[tn][h2].x + aZ[tn][h2 * 2]     + bzv[tn].x)));
                    float z1 = 1.f / (1.f + expf(-(gz[tn][h2].y + aZ[tn][h2 * 2 + 1] + bzv[tn].y)));
                    float c0 = tanhf(gh[tn][h2].x + aH[tn][h2 * 2]     + bhv[tn].x);
                    float c1 = tanhf(gh[tn][h2].y + aH[tn][h2 * 2 + 1] + bhv[tn].y);
                    S[tn][h2 * 2]     = (1.f - z0) * S[tn][h2 * 2]     + z0 * c0;
                    S[tn][h2 * 2 + 1] = (1.f - z1) * S[tn][h2 * 2 + 1] + z1 * c1;
                }
            if (t > 0 && t + 1 < NT) BARH(barid);  // gemm reads done before next write
        }

#pragma unroll
        for (int tn = 0; tn < 4; tn++)
#pragma unroll
            for (int h2 = 0; h2 < 2; h2++) {
                int grow = tile * 32 + rowsl[h2];
                *(float2*)(out + (size_t)grow * D + cols[tn]) =
                    make_float2(S[tn][h2 * 2], S[tn][h2 * 2 + 1]);
            }
    }
}

// ---------------------------------------------------------------------------
extern "C" void kernel_launch(void* const* d_in, const int* in_sizes, int n_in,
                              void* d_out, int out_size) {
    const int*   ei       = (const int*)d_in[0];
    const int*   src      = ei;
    const int*   dst      = ei + NE;
    const int*   etype    = (const int*)d_in[1];
    const int*   etime    = (const int*)d_in[2];
    const float* ew       = (const float*)d_in[3];
    const float* node_emb = (const float*)d_in[4];
    const float* rel_emb  = (const float*)d_in[5];
    const float* Wenc     = (const float*)d_in[6];
    const float* Wz       = (const float*)d_in[7];
    const float* Uz       = (const float*)d_in[8];
    const float* Wh       = (const float*)d_in[9];
    const float* Uh       = (const float*)d_in[10];
    const float* bz       = (const float*)d_in[11];
    const float* bh       = (const float*)d_in[12];

    cudaFuncSetAttribute(enc_gates, cudaFuncAttributeMaxDynamicSharedMemorySize, SMEM_ENC);
    cudaFuncSetAttribute(step_all,  cudaFuncAttributeMaxDynamicSharedMemorySize, SMEM_STEP);

    void* aggp = nullptr;
    cudaGetSymbolAddress(&aggp, g_agg);
    cudaMemsetAsync(aggp, 0, (size_t)NT * NRP * D * sizeof(float), 0);

    prep_weights<<<(5 * 128 * 128 + 255) / 256, 256>>>(Wenc, Wz, Uz, Wh, Uh);
    scatter_kernel<<<(NE * 32 + 255) / 256, 256>>>(src, dst, etype, etime, ew,
                                                   node_emb, rel_emb);

    enc_gates<<<148, 512, SMEM_ENC>>>();
    step_all<<<148, 512, SMEM_STEP>>>(bz, bh, (float*)d_out);
}

// round 12
// speedup vs baseline: 2.1060x; 1.0531x over previous
#include <cuda_runtime.h>
#include <cuda_bf16.h>
#include <cstdint>

#define NN 20000    // nodes
#define D  128      // dim
#define NE 200000   // edges
#define NT 8        // timesteps
#define NRP 20096   // padded rows (157*128)
#define NTIL64 314  // 64-row tiles (NRP/64)
#define NTT (NT * NTIL64)   // 2512 (t,tile) pairs for enc_gates
#define NTIL32 625  // 32-row tiles for step_all (exact: 625*32 = 20000)
#define PAD 136     // bf16 elems per padded smem row (step_all layout)

// ---- static device scratch (no runtime allocation) ----
__device__ float g_agg[(size_t)NT * NRP * D];  // per-time aggregated messages
__device__ uint4 g_Wp[5 * 2 * 128 * 16];       // 5 weights x {hi,lo} x [n][k] bf16 linear
__device__ float g_GZ[(size_t)NT * NRP * D];   // H@Wz (fp32 preact)
__device__ float g_GH[(size_t)NT * NRP * D];   // H@Wh

// ---- enc_gates smem (XOR-swizzled 256B rows; weight splits are 32KB each) ----
#define EX_HI 0
#define EX_LO 16384
#define EWE_HI 32768
#define EWE_LO 65536
#define EWZ_HI 98304
#define EWZ_LO 131072
#define EWH_HI 163840
#define EWH_LO 196608
#define SMEM_ENC 229376

// ---- step_all smem: Uz + Uh (padded rows) + per-group SX buffers ----
#define SW0_HI 0
#define SW0_LO 34816
#define SW1_HI 69632
#define SW1_LO 104448
#define SXBASE 139264
#define SXG 17408            // per-group SX size (hi 8704 + lo 8704)
#define SMEM_STEP (SXBASE + 2 * SXG)   // 174080

// ---------------------------------------------------------------------------
__device__ __forceinline__ uint32_t smem_u32(const void* p) {
    uint32_t a;
    asm("{ .reg .u64 t; cvta.to.shared.u64 t, %1; cvt.u32.u64 %0, t; }" : "=r"(a) : "l"(p));
    return a;
}

#define LDSM4(R, a) \
    asm volatile("ldmatrix.sync.aligned.m8n8.x4.shared.b16 {%0,%1,%2,%3}, [%4];" \
                 : "=r"((R)[0]), "=r"((R)[1]), "=r"((R)[2]), "=r"((R)[3]) : "r"(a))

#define MMA16816(d, a, b0, b1) \
    asm volatile("mma.sync.aligned.m16n8k16.row.col.f32.bf16.bf16.f32 " \
                 "{%0,%1,%2,%3},{%4,%5,%6,%7},{%8,%9},{%0,%1,%2,%3};" \
                 : "+f"((d)[0]), "+f"((d)[1]), "+f"((d)[2]), "+f"((d)[3]) \
                 : "r"((a)[0]), "r"((a)[1]), "r"((a)[2]), "r"((a)[3]), "r"(b0), "r"(b1))

#define BARH(id) asm volatile("bar.sync %0, 128;" :: "r"(id) : "memory")

__device__ __forceinline__ void split2(float x, float y, uint32_t& h, uint32_t& l) {
    __nv_bfloat16 hx = __float2bfloat16(x), hy = __float2bfloat16(y);
    float rx = x - __bfloat162float(hx);
    float ry = y - __bfloat162float(hy);
    __nv_bfloat16 lx = __float2bfloat16(rx), ly = __float2bfloat16(ry);
    h = (uint32_t)__bfloat16_as_ushort(hx) | ((uint32_t)__bfloat16_as_ushort(hy) << 16);
    l = (uint32_t)__bfloat16_as_ushort(lx) | ((uint32_t)__bfloat16_as_ushort(ly) << 16);
}

// Fast MUFU-based transcendentals (rel err ~1e-6; inf-safe saturation)
__device__ __forceinline__ float fsig(float x) {
    return __fdividef(1.f, 1.f + __expf(-x));
}
__device__ __forceinline__ float ftanh(float x) {
    return 1.f - __fdividef(2.f, __expf(2.f * x) + 1.f);
}

// ---------------------------------------------------------------------------
__global__ void prep_weights(const float* W0, const float* W1, const float* W2,
                             const float* W3, const float* W4) {
    int idx = blockIdx.x * blockDim.x + threadIdx.x;
    if (idx >= 5 * 128 * 128) return;
    int w = idx >> 14, rem = idx & 16383, n = rem >> 7, k = rem & 127;
    const float* Ws = (w == 0) ? W0 : (w == 1) ? W1 : (w == 2) ? W2 : (w == 3) ? W3 : W4;
    float v = Ws[k * 128 + n];
    __nv_bfloat16 hv = __float2bfloat16(v);
    float res = v - __bfloat162float(hv);
    __nv_bfloat16 lv = __float2bfloat16(res);
    unsigned short* base = (unsigned short*)g_Wp;
    base[(size_t)((w * 2 + 0) * 128 + n) * 128 + k] = __bfloat16_as_ushort(hv);
    base[(size_t)((w * 2 + 1) * 128 + n) * 128 + k] = __bfloat16_as_ushort(lv);
}

__global__ void scatter_kernel(const int* __restrict__ src, const int* __restrict__ dst,
                               const int* __restrict__ etype, const int* __restrict__ etime,
                               const float* __restrict__ ew,
                               const float* __restrict__ node_emb,
                               const float* __restrict__ rel_emb) {
    int gid  = blockIdx.x * blockDim.x + threadIdx.x;
    int e    = gid >> 5;
    int lane = gid & 31;
    if (e >= NE) return;
    int t = etime[e];
    if ((unsigned)t >= NT) return;
    int s = src[e], d = dst[e], r = etype[e];
    float w = ew[e];
    float4 a = reinterpret_cast<const float4*>(node_emb + (size_t)s * D)[lane];
    float4 b = reinterpret_cast<const float4*>(rel_emb  + (size_t)r * D)[lane];
    float* o = g_agg + ((size_t)t * NRP + d) * D + lane * 4;
    asm volatile("red.global.add.v4.f32 [%0], {%1,%2,%3,%4};"
                 :: "l"(o), "f"(a.x * b.x * w), "f"(a.y * b.y * w),
                    "f"(a.z * b.z * w), "f"(a.w * b.w * w) : "memory");
}

// ---------------------------------------------------------------------------
// enc_gates: fused H = tanh(agg@Wenc) smem-only, then dual GZ/GH GEMM sharing
// H fragments. 64-row tiles, 512 thr, XOR-swizzle 256B rows.
// ---------------------------------------------------------------------------
__device__ __forceinline__ void copy_w_swz(char* sm_, int w, int tid,
                                           int hi_off, int lo_off) {
    const uint4* s = g_Wp + (size_t)w * 4096;
    for (int i = tid; i < 4096; i += 512) {
        int sp = i >> 11, j = i & 2047, n = j >> 4, c = j & 15;
        uint32_t off = (uint32_t)(n * 256) + (((c ^ (n & 7)) & 15) << 4);
        *(uint4*)(sm_ + (sp ? lo_off : hi_off) + off) = s[i];
    }
}

__device__ __forceinline__ void gemm64sw(float (&acc)[2][2][4],
                                         uint32_t xhi, uint32_t xlo,
                                         uint32_t whi, uint32_t wlo,
                                         int lane, int wm, int wn) {
    int ar = wm * 32 + (lane & 15);
    int ach = lane >> 4;
    int brow = wn * 16 + (lane & 7) + ((lane >> 4) & 1) * 8;
    int bch = (lane >> 3) & 1;
    uint32_t ab0 = (uint32_t)(ar * 256), ab1 = (uint32_t)((ar + 16) * 256);
    int am = ar & 7;
    uint32_t bb = (uint32_t)(brow * 256);
    int bm = brow & 7;
#pragma unroll 2
    for (int ks = 0; ks < 8; ks++) {
        uint32_t Ah[2][4], Al[2][4], Bh[4], Bl[4];
        uint32_t ao = (uint32_t)((((ks * 2 + ach) ^ am) & 15) << 4);
        uint32_t bo = (uint32_t)((((ks * 2 + bch) ^ bm) & 15) << 4);
        LDSM4(Ah[0], xhi + ab0 + ao);
        LDSM4(Al[0], xlo + ab0 + ao);
        LDSM4(Ah[1], xhi + ab1 + ao);
        LDSM4(Al[1], xlo + ab1 + ao);
        LDSM4(Bh, whi + bb + bo);
        LDSM4(Bl, wlo + bb + bo);
#pragma unroll
        for (int tm = 0; tm < 2; tm++)
#pragma unroll
            for (int tn = 0; tn < 2; tn++) {
                int o = tn * 2;
                MMA16816(acc[tm][tn], Ah[tm], Bh[o], Bh[o + 1]);
                MMA16816(acc[tm][tn], Al[tm], Bh[o], Bh[o + 1]);
                MMA16816(acc[tm][tn], Ah[tm], Bl[o], Bl[o + 1]);
            }
    }
}

__device__ __forceinline__ void gemm64sw_dual(float (&aZ)[2][2][4], float (&aH)[2][2][4],
                                              uint32_t xhi, uint32_t xlo,
                                              uint32_t zhi, uint32_t zlo,
                                              uint32_t hhi, uint32_t hlo,
                                              int lane, int wm, int wn) {
    int ar = wm * 32 + (lane & 15);
    int ach = lane >> 4;
    int brow = wn * 16 + (lane & 7) + ((lane >> 4) & 1) * 8;
    int bch = (lane >> 3) & 1;
    uint32_t ab0 = (uint32_t)(ar * 256), ab1 = (uint32_t)((ar + 16) * 256);
    int am = ar & 7;
    uint32_t bb = (uint32_t)(brow * 256);
    int bm = brow & 7;
#pragma unroll 1
    for (int ks = 0; ks < 8; ks++) {
        uint32_t Ah[2][4], Al[2][4], Bzh[4], Bzl[4], Bhh[4], Bhl[4];
        uint32_t ao = (uint32_t)((((ks * 2 + ach) ^ am) & 15) << 4);
        uint32_t bo = (uint32_t)((((ks * 2 + bch) ^ bm) & 15) << 4);
        LDSM4(Ah[0], xhi + ab0 + ao);
        LDSM4(Al[0], xlo + ab0 + ao);
        LDSM4(Ah[1], xhi + ab1 + ao);
        LDSM4(Al[1], xlo + ab1 + ao);
        LDSM4(Bzh, zhi + bb + bo);
        LDSM4(Bzl, zlo + bb + bo);
        LDSM4(Bhh, hhi + bb + bo);
        LDSM4(Bhl, hlo + bb + bo);
#pragma unroll
        for (int tm = 0; tm < 2; tm++)
#pragma unroll
            for (int tn = 0; tn < 2; tn++) {
                int o = tn * 2;
                MMA16816(aZ[tm][tn], Ah[tm], Bzh[o], Bzh[o + 1]);
                MMA16816(aZ[tm][tn], Al[tm], Bzh[o], Bzh[o + 1]);
                MMA16816(aZ[tm][tn], Ah[tm], Bzl[o], Bzl[o + 1]);
                MMA16816(aH[tm][tn], Ah[tm], Bhh[o], Bhh[o + 1]);
                MMA16816(aH[tm][tn], Al[tm], Bhh[o], Bhh[o + 1]);
                MMA16816(aH[tm][tn], Ah[tm], Bhl[o], Bhl[o + 1]);
            }
    }
}

#define ZERO_ACC224(acc) \
    { _Pragma("unroll") for (int i = 0; i < 2; i++) \
      _Pragma("unroll") for (int j = 0; j < 2; j++) \
      _Pragma("unroll") for (int q = 0; q < 4; q++) (acc)[i][j][q] = 0.f; }

__global__ void __launch_bounds__(512, 1) enc_gates() {
    extern __shared__ char sm[];
    uint32_t sb = smem_u32(sm);
    int tid = threadIdx.x, lane = tid & 31, wid = tid >> 5;
    int wm = wid & 1, wn = wid >> 1;

    copy_w_swz(sm, 0, tid, EWE_HI, EWE_LO);
    copy_w_swz(sm, 1, tid, EWZ_HI, EWZ_LO);
    copy_w_swz(sm, 3, tid, EWH_HI, EWH_LO);

    int xrow = tid >> 3, xseg = (tid & 7) * 16;
    int xc0 = xseg >> 3;

    float4 pf[4];
    {
        int tt = blockIdx.x;
        int t = tt / NTIL64, tile = tt - t * NTIL64;
        const float4* s = (const float4*)(g_agg + ((size_t)t * NRP + tile * 64 + xrow) * D + xseg);
#pragma unroll
        for (int q = 0; q < 4; q++) pf[q] = s[q];
    }

    for (int tt = blockIdx.x; tt < NTT; tt += gridDim.x) {
        int t = tt / NTIL64, tile = tt - t * NTIL64;

        __syncthreads();
#pragma unroll
        for (int g = 0; g < 2; g++) {
            float4 a = pf[g * 2], b = pf[g * 2 + 1];
            uint32_t h0, h1, h2, h3, l0, l1, l2, l3;
            split2(a.x, a.y, h0, l0);
            split2(a.z, a.w, h1, l1);
            split2(b.x, b.y, h2, l2);
            split2(b.z, b.w, h3, l3);
            uint32_t off = (uint32_t)(xrow * 256) + ((((xc0 + g) ^ (xrow & 7)) & 15) << 4);
            *(uint4*)(sm + EX_HI + off) = make_uint4(h0, h1, h2, h3);
            *(uint4*)(sm + EX_LO + off) = make_uint4(l0, l1, l2, l3);
        }
        __syncthreads();

        float acc[2][2][4];
        ZERO_ACC224(acc);
        gemm64sw(acc, sb + EX_HI, sb + EX_LO, sb + EWE_HI, sb + EWE_LO, lane, wm, wn);
        __syncthreads();

#pragma unroll
        for (int tm = 0; tm < 2; tm++)
#pragma unroll
            for (int tn = 0; tn < 2; tn++) {
                int c = wn * 16 + tn * 8 + (lane & 3) * 2;
#pragma unroll
                for (int h2i = 0; h2i < 2; h2i++) {
                    int r = wm * 32 + tm * 16 + (lane >> 2) + h2i * 8;
                    uint32_t h, l;
                    split2(ftanh(acc[tm][tn][h2i * 2]), ftanh(acc[tm][tn][h2i * 2 + 1]), h, l);
                    uint32_t off = (uint32_t)(r * 256) + ((((c >> 3) ^ (r & 7)) & 15) << 4)
                                 + (uint32_t)((c & 7) * 2);
                    *(uint32_t*)(sm + EX_HI + off) = h;
                    *(uint32_t*)(sm + EX_LO + off) = l;
                }
            }
        __syncthreads();

        if (tt + (int)gridDim.x < NTT) {
            int nt2 = tt + gridDim.x;
            int t2 = nt2 / NTIL64, tile2 = nt2 - t2 * NTIL64;
            const float4* s = (const float4*)(g_agg + ((size_t)t2 * NRP + tile2 * 64 + xrow) * D + xseg);
#pragma unroll
            for (int q = 0; q < 4; q++) pf[q] = s[q];
        }

        float accZ[2][2][4], accH[2][2][4];
        ZERO_ACC224(accZ);
        ZERO_ACC224(accH);
        gemm64sw_dual(accZ, accH, sb + EX_HI, sb + EX_LO,
                      sb + EWZ_HI, sb + EWZ_LO, sb + EWH_HI, sb + EWH_LO, lane, wm, wn);

        size_t base = (size_t)t * NRP + (size_t)tile * 64;
#pragma unroll
        for (int tm = 0; tm < 2; tm++)
#pragma unroll
            for (int tn = 0; tn < 2; tn++) {
                int c = wn * 16 + tn * 8 + (lane & 3) * 2;
#pragma unroll
                for (int h2i = 0; h2i < 2; h2i++) {
                    int r = wm * 32 + tm * 16 + (lane >> 2) + h2i * 8;
                    *(float2*)(g_GZ + (base + r) * D + c) =
                        make_float2(accZ[tm][tn][h2i * 2], accZ[tm][tn][h2i * 2 + 1]);
                    *(float2*)(g_GH + (base + r) * D + c) =
                        make_float2(accH[tm][tn][h2i * 2], accH[tm][tn][h2i * 2 + 1]);
                }
            }
    }
}

// ---------------------------------------------------------------------------
// step_all: 2 groups/CTA x 2 wm-halves = 4 sync domains (named bar.sync, 128
// thr). Group owns a 32-row tile stream; warp tile 16m x 32n. State in
// registers across t; gz/gh loaded directly (early-issued).
// ---------------------------------------------------------------------------
__device__ __forceinline__ void copy_w_pad(char* sm_, int w, int tid,
                                           int hi_off, int lo_off) {
    const uint4* s = g_Wp + (size_t)w * 4096;
    for (int i = tid; i < 4096; i += 512) {
        int sp = i >> 11, j = i & 2047, n = j >> 4, kk = j & 15;
        *(uint4*)(sm_ + (sp ? lo_off : hi_off) + (uint32_t)(n * PAD + kk * 8) * 2) = s[i];
    }
}

__device__ __forceinline__ void gemm_step_dual(float (&aZ)[4][4], float (&aH)[4][4],
                                               uint32_t xhi, uint32_t xlo,
                                               uint32_t zhi, uint32_t zlo,
                                               uint32_t hhi, uint32_t hlo,
                                               int lane, int wm, int wn) {
    const int arow = wm * 16 + (lane & 15);
    const int acolo = (lane >> 4) * 8;
    const int brow = wn * 32 + (lane & 7) + ((lane >> 4) & 1) * 8;
    const int bcolo = ((lane >> 3) & 1) * 8;
    const uint32_t bstep = (uint32_t)(16 * PAD) * 2;
#pragma unroll 1
    for (int ks = 0; ks < 8; ks++) {
        uint32_t Ah[4], Al[4], Bzh[8], Bzl[8], Bhh[8], Bhl[8];
        uint32_t ao = (uint32_t)(arow * PAD + ks * 16 + acolo) * 2;
        uint32_t bo = (uint32_t)(brow * PAD + ks * 16 + bcolo) * 2;
        LDSM4(Ah, xhi + ao);
        LDSM4(Al, xlo + ao);
        LDSM4(Bzh, zhi + bo);
        LDSM4(Bzh + 4, zhi + bo + bstep);
        LDSM4(Bzl, zlo + bo);
        LDSM4(Bzl + 4, zlo + bo + bstep);
        LDSM4(Bhh, hhi + bo);
        LDSM4(Bhh + 4, hhi + bo + bstep);
        LDSM4(Bhl, hlo + bo);
        LDSM4(Bhl + 4, hlo + bo + bstep);
#pragma unroll
        for (int tn = 0; tn < 4; tn++) {
            int o = tn * 2;
            MMA16816(aZ[tn], Ah, Bzh[o], Bzh[o + 1]);
            MMA16816(aZ[tn], Al, Bzh[o], Bzh[o + 1]);
            MMA16816(aZ[tn], Ah, Bzl[o], Bzl[o + 1]);
            MMA16816(aH[tn], Ah, Bhh[o], Bhh[o + 1]);
            MMA16816(aH[tn], Al, Bhh[o], Bhh[o + 1]);
            MMA16816(aH[tn], Ah, Bhl[o], Bhl[o + 1]);
        }
    }
}

__global__ void __launch_bounds__(512, 1) step_all(const float* __restrict__ bz,
                                                   const float* __restrict__ bh,
                                                   float* __restrict__ out) {
    extern __shared__ char sm[];
    uint32_t sb = smem_u32(sm);
    int tid = threadIdx.x, lane = tid & 31, wid = tid >> 5;
    int grp = wid >> 3;
    int lw = wid & 7;
    int wm = lw & 1, wn = lw >> 1;
    int barid = 1 + grp * 2 + wm;

    copy_w_pad(sm, 2, tid, SW0_HI, SW0_LO);  // Uz
    copy_w_pad(sm, 4, tid, SW1_HI, SW1_LO);  // Uh

    uint32_t sxhi = sb + SXBASE + grp * SXG;
    uint32_t sxlo = sxhi + 8704;

    int cols[4];
#pragma unroll
    for (int tn = 0; tn < 4; tn++) cols[tn] = wn * 32 + tn * 8 + (lane & 3) * 2;
    int rowsl[2];
#pragma unroll
    for (int h2 = 0; h2 < 2; h2++) rowsl[h2] = wm * 16 + (lane >> 2) + h2 * 8;

    float2 bzv[4], bhv[4];
#pragma unroll
    for (int tn = 0; tn < 4; tn++) {
        bzv[tn] = *(const float2*)(bz + cols[tn]);
        bhv[tn] = *(const float2*)(bh + cols[tn]);
    }
    __syncthreads();  // weights ready (only full-CTA barrier)

    for (int tile = blockIdx.x * 2 + grp; tile < NTIL32; tile += 296) {
        float S[4][4];
#pragma unroll
        for (int tn = 0; tn < 4; tn++)
#pragma unroll
            for (int q = 0; q < 4; q++) S[tn][q] = 0.f;

        for (int t = 0; t < NT; t++) {
            size_t base = (size_t)t * NRP + (size_t)tile * 32;
            float2 gz[4][2], gh[4][2];
#pragma unroll
            for (int tn = 0; tn < 4; tn++)
#pragma unroll
                for (int h2 = 0; h2 < 2; h2++) {
                    size_t idx = (base + rowsl[h2]) * D + cols[tn];
                    gz[tn][h2] = *(const float2*)(g_GZ + idx);
                    gh[tn][h2] = *(const float2*)(g_GH + idx);
                }

            float aZ[4][4], aH[4][4];
#pragma unroll
            for (int tn = 0; tn < 4; tn++)
#pragma unroll
                for (int q = 0; q < 4; q++) { aZ[tn][q] = 0.f; aH[tn][q] = 0.f; }

            if (t > 0) {
#pragma unroll
                for (int tn = 0; tn < 4; tn++)
#pragma unroll
                    for (int h2 = 0; h2 < 2; h2++) {
                        uint32_t h, l;
                        split2(S[tn][h2 * 2], S[tn][h2 * 2 + 1], h, l);
                        uint32_t off = (uint32_t)(rowsl[h2] * PAD + cols[tn]) * 2;
                        *(uint32_t*)(sm + SXBASE + grp * SXG + off) = h;
                        *(uint32_t*)(sm + SXBASE + grp * SXG + 8704 + off) = l;
                    }
                BARH(barid);
                gemm_step_dual(aZ, aH, sxhi, sxlo,
                               sb + SW0_HI, sb + SW0_LO, sb + SW1_HI, sb + SW1_LO,
                               lane, wm, wn);
            }

#pragma unroll
            for (int tn = 0; tn < 4; tn++)
#pragma unroll
                for (int h2 = 0; h2 < 2; h2++) {
                    float z0 = fsig(gz[tn][h2].x + aZ[tn][h2 * 2]     + bzv[tn].x);
                    float z1 = fsig(gz[tn][h2].y + aZ[tn][h2 * 2 + 1] + bzv[tn].y);
                    float c0 = ftanh(gh[tn][h2].x + aH[tn][h2 * 2]     + bhv[tn].x);
                    float c1 = ftanh(gh[tn][h2].y + aH[tn][h2 * 2 + 1] + bhv[tn].y);
                    S[tn][h2 * 2]     = (1.f - z0) * S[tn][h2 * 2]     + z0 * c0;
                    S[tn][h2 * 2 + 1] = (1.f - z1) * S[tn][h2 * 2 + 1] + z1 * c1;
                }
            if (t > 0 && t + 1 < NT) BARH(barid);
        }

#pragma unroll
        for (int tn = 0; tn < 4; tn++)
#pragma unroll
            for (int h2 = 0; h2 < 2; h2++) {
                int grow = tile * 32 + rowsl[h2];
                *(float2*)(out + (size_t)grow * D + cols[tn]) =
                    make_float2(S[tn][h2 * 2], S[tn][h2 * 2 + 1]);
            }
    }
}

// ---------------------------------------------------------------------------
extern "C" void kernel_launch(void* const* d_in, const int* in_sizes, int n_in,
                              void* d_out, int out_size) {
    const int*   ei       = (const int*)d_in[0];
    const int*   src      = ei;
    const int*   dst      = ei + NE;
    const int*   etype    = (const int*)d_in[1];
    const int*   etime    = (const int*)d_in[2];
    const float* ew       = (const float*)d_in[3];
    const float* node_emb = (const float*)d_in[4];
    const float* rel_emb  = (const float*)d_in[5];
    const float* Wenc     = (const float*)d_in[6];
    const float* Wz       = (const float*)d_in[7];
    const float* Uz       = (const float*)d_in[8];
    const float* Wh       = (const float*)d_in[9];
    const float* Uh       = (const float*)d_in[10];
    const float* bz       = (const float*)d_in[11];
    const float* bh       = (const float*)d_in[12];

    cudaFuncSetAttribute(enc_gates, cudaFuncAttributeMaxDynamicSharedMemorySize, SMEM_ENC);
    cudaFuncSetAttribute(step_all,  cudaFuncAttributeMaxDynamicSharedMemorySize, SMEM_STEP);

    void* aggp = nullptr;
    cudaGetSymbolAddress(&aggp, g_agg);
    cudaMemsetAsync(aggp, 0, (size_t)NT * NRP * D * sizeof(float), 0);

    prep_weights<<<(5 * 128 * 128 + 255) / 256, 256>>>(Wenc, Wz, Uz, Wh, Uh);
    scatter_kernel<<<(NE * 32 + 255) / 256, 256>>>(src, dst, etype, etime, ew,
                                                   node_emb, rel_emb);

    enc_gates<<<148, 512, SMEM_ENC>>>();
    step_all<<<148, 512, SMEM_STEP>>>(bz, bh, (float*)d_out);
}

// round 14
// speedup vs baseline: 2.1556x; 1.0235x over previous
#include <cuda_runtime.h>
#include <cuda_bf16.h>
#include <cuda_fp16.h>
#include <cstdint>

#define NN 20000    // nodes
#define D  128      // dim
#define NE 200000   // edges
#define NT 8        // timesteps
#define NRP 20096   // padded rows (157*128)
#define NTIL64 314  // 64-row tiles (NRP/64)
#define NTT (NT * NTIL64)   // 2512 (t,tile) pairs for enc_gates
#define NTIL32 625  // 32-row tiles for step_all (exact: 625*32 = 20000)
#define PAD 136     // bf16 elems per padded smem row (step_all layout)

// ---- static device scratch (no runtime allocation) ----
__device__ float  g_agg[(size_t)NT * NRP * D];  // per-time aggregated messages
__device__ uint4  g_Wp[5 * 2 * 128 * 16];       // 5 weights x {hi,lo} x [n][k] bf16 linear
__device__ __half g_GZ[(size_t)NT * NRP * D];   // H@Wz (fp16 preact)
__device__ __half g_GH[(size_t)NT * NRP * D];   // H@Wh

// ---- enc_gates smem (XOR-swizzled 256B rows; weight splits are 32KB each) ----
#define EX_HI 0
#define EX_LO 16384
#define EWE_HI 32768
#define EWE_LO 65536
#define EWZ_HI 98304
#define EWZ_LO 131072
#define EWH_HI 163840
#define EWH_LO 196608
#define SMEM_ENC 229376

// ---- step_all smem: Uz + Uh (padded rows) + per-group SX buffers ----
#define SW0_HI 0
#define SW0_LO 34816
#define SW1_HI 69632
#define SW1_LO 104448
#define SXBASE 139264
#define SXG 17408            // per-group SX size (hi 8704 + lo 8704)
#define SMEM_STEP (SXBASE + 2 * SXG)   // 174080

// ---------------------------------------------------------------------------
__device__ __forceinline__ uint32_t smem_u32(const void* p) {
    uint32_t a;
    asm("{ .reg .u64 t; cvta.to.shared.u64 t, %1; cvt.u32.u64 %0, t; }" : "=r"(a) : "l"(p));
    return a;
}

#define LDSM4(R, a) \
    asm volatile("ldmatrix.sync.aligned.m8n8.x4.shared.b16 {%0,%1,%2,%3}, [%4];" \
                 : "=r"((R)[0]), "=r"((R)[1]), "=r"((R)[2]), "=r"((R)[3]) : "r"(a))

#define MMA16816(d, a, b0, b1) \
    asm volatile("mma.sync.aligned.m16n8k16.row.col.f32.bf16.bf16.f32 " \
                 "{%0,%1,%2,%3},{%4,%5,%6,%7},{%8,%9},{%0,%1,%2,%3};" \
                 : "+f"((d)[0]), "+f"((d)[1]), "+f"((d)[2]), "+f"((d)[3]) \
                 : "r"((a)[0]), "r"((a)[1]), "r"((a)[2]), "r"((a)[3]), "r"(b0), "r"(b1))

#define BARH(id) asm volatile("bar.sync %0, 128;" :: "r"(id) : "memory")

__device__ __forceinline__ void split2(float x, float y, uint32_t& h, uint32_t& l) {
    __nv_bfloat16 hx = __float2bfloat16(x), hy = __float2bfloat16(y);
    float rx = x - __bfloat162float(hx);
    float ry = y - __bfloat162float(hy);
    __nv_bfloat16 lx = __float2bfloat16(rx), ly = __float2bfloat16(ry);
    h = (uint32_t)__bfloat16_as_ushort(hx) | ((uint32_t)__bfloat16_as_ushort(hy) << 16);
    l = (uint32_t)__bfloat16_as_ushort(lx) | ((uint32_t)__bfloat16_as_ushort(ly) << 16);
}

// Fast MUFU-based transcendentals (rel err ~1e-6; inf-safe saturation)
__device__ __forceinline__ float fsig(float x) {
    return __fdividef(1.f, 1.f + __expf(-x));
}
__device__ __forceinline__ float ftanh(float x) {
    return 1.f - __fdividef(2.f, __expf(2.f * x) + 1.f);
}

// ---------------------------------------------------------------------------
__global__ void prep_weights(const float* W0, const float* W1, const float* W2,
                             const float* W3, const float* W4) {
    int idx = blockIdx.x * blockDim.x + threadIdx.x;
    if (idx >= 5 * 128 * 128) return;
    int w = idx >> 14, rem = idx & 16383, n = rem >> 7, k = rem & 127;
    const float* Ws = (w == 0) ? W0 : (w == 1) ? W1 : (w == 2) ? W2 : (w == 3) ? W3 : W4;
    float v = Ws[k * 128 + n];
    __nv_bfloat16 hv = __float2bfloat16(v);
    float res = v - __bfloat162float(hv);
    __nv_bfloat16 lv = __float2bfloat16(res);
    unsigned short* base = (unsigned short*)g_Wp;
    base[(size_t)((w * 2 + 0) * 128 + n) * 128 + k] = __bfloat16_as_ushort(hv);
    base[(size_t)((w * 2 + 1) * 128 + n) * 128 + k] = __bfloat16_as_ushort(lv);
}

__global__ void scatter_kernel(const int* __restrict__ src, const int* __restrict__ dst,
                               const int* __restrict__ etype, const int* __restrict__ etime,
                               const float* __restrict__ ew,
                               const float* __restrict__ node_emb,
                               const float* __restrict__ rel_emb) {
    int gid  = blockIdx.x * blockDim.x + threadIdx.x;
    int e    = gid >> 5;
    int lane = gid & 31;
    if (e >= NE) return;
    int t = etime[e];
    if ((unsigned)t >= NT) return;
    int s = src[e], d = dst[e], r = etype[e];
    float w = ew[e];
    float4 a = reinterpret_cast<const float4*>(node_emb + (size_t)s * D)[lane];
    float4 b = reinterpret_cast<const float4*>(rel_emb  + (size_t)r * D)[lane];
    float* o = g_agg + ((size_t)t * NRP + d) * D + lane * 4;
    asm volatile("red.global.add.v4.f32 [%0], {%1,%2,%3,%4};"
                 :: "l"(o), "f"(a.x * b.x * w), "f"(a.y * b.y * w),
                    "f"(a.z * b.z * w), "f"(a.w * b.w * w) : "memory");
}

// ---------------------------------------------------------------------------
// enc_gates: fused H = tanh(agg@Wenc) smem-only, then dual GZ/GH GEMM sharing
// H fragments. 64-row tiles, 512 thr, XOR-swizzle 256B rows. fp16 outputs.
// ---------------------------------------------------------------------------
__device__ __forceinline__ void copy_w_swz(char* sm_, int w, int tid,
                                           int hi_off, int lo_off) {
    const uint4* s = g_Wp + (size_t)w * 4096;
    for (int i = tid; i < 4096; i += 512) {
        int sp = i >> 11, j = i & 2047, n = j >> 4, c = j & 15;
        uint32_t off = (uint32_t)(n * 256) + (((c ^ (n & 7)) & 15) << 4);
        *(uint4*)(sm_ + (sp ? lo_off : hi_off) + off) = s[i];
    }
}

__device__ __forceinline__ void gemm64sw(float (&acc)[2][2][4],
                                         uint32_t xhi, uint32_t xlo,
                                         uint32_t whi, uint32_t wlo,
                                         int lane, int wm, int wn) {
    int ar = wm * 32 + (lane & 15);
    int ach = lane >> 4;
    int brow = wn * 16 + (lane & 7) + ((lane >> 4) & 1) * 8;
    int bch = (lane >> 3) & 1;
    uint32_t ab0 = (uint32_t)(ar * 256), ab1 = (uint32_t)((ar + 16) * 256);
    int am = ar & 7;
    uint32_t bb = (uint32_t)(brow * 256);
    int bm = brow & 7;
#pragma unroll 2
    for (int ks = 0; ks < 8; ks++) {
        uint32_t Ah[2][4], Al[2][4], Bh[4], Bl[4];
        uint32_t ao = (uint32_t)((((ks * 2 + ach) ^ am) & 15) << 4);
        uint32_t bo = (uint32_t)((((ks * 2 + bch) ^ bm) & 15) << 4);
        LDSM4(Ah[0], xhi + ab0 + ao);
        LDSM4(Al[0], xlo + ab0 + ao);
        LDSM4(Ah[1], xhi + ab1 + ao);
        LDSM4(Al[1], xlo + ab1 + ao);
        LDSM4(Bh, whi + bb + bo);
        LDSM4(Bl, wlo + bb + bo);
#pragma unroll
        for (int tm = 0; tm < 2; tm++)
#pragma unroll
            for (int tn = 0; tn < 2; tn++) {
                int o = tn * 2;
                MMA16816(acc[tm][tn], Ah[tm], Bh[o], Bh[o + 1]);
                MMA16816(acc[tm][tn], Al[tm], Bh[o], Bh[o + 1]);
                MMA16816(acc[tm][tn], Ah[tm], Bl[o], Bl[o + 1]);
            }
    }
}

__device__ __forceinline__ void gemm64sw_dual(float (&aZ)[2][2][4], float (&aH)[2][2][4],
                                              uint32_t xhi, uint32_t xlo,
                                              uint32_t zhi, uint32_t zlo,
                                              uint32_t hhi, uint32_t hlo,
                                              int lane, int wm, int wn) {
    int ar = wm * 32 + (lane & 15);
    int ach = lane >> 4;
    int brow = wn * 16 + (lane & 7) + ((lane >> 4) & 1) * 8;
    int bch = (lane >> 3) & 1;
    uint32_t ab0 = (uint32_t)(ar * 256), ab1 = (uint32_t)((ar + 16) * 256);
    int am = ar & 7;
    uint32_t bb = (uint32_t)(brow * 256);
    int bm = brow & 7;
#pragma unroll 1
    for (int ks = 0; ks < 8; ks++) {
        uint32_t Ah[2][4], Al[2][4], Bzh[4], Bzl[4], Bhh[4], Bhl[4];
        uint32_t ao = (uint32_t)((((ks * 2 + ach) ^ am) & 15) << 4);
        uint32_t bo = (uint32_t)((((ks * 2 + bch) ^ bm) & 15) << 4);
        LDSM4(Ah[0], xhi + ab0 + ao);
        LDSM4(Al[0], xlo + ab0 + ao);
        LDSM4(Ah[1], xhi + ab1 + ao);
        LDSM4(Al[1], xlo + ab1 + ao);
        LDSM4(Bzh, zhi + bb + bo);
        LDSM4(Bzl, zlo + bb + bo);
        LDSM4(Bhh, hhi + bb + bo);
        LDSM4(Bhl, hlo + bb + bo);
#pragma unroll
        for (int tm = 0; tm < 2; tm++)
#pragma unroll
            for (int tn = 0; tn < 2; tn++) {
                int o = tn * 2;
                MMA16816(aZ[tm][tn], Ah[tm], Bzh[o], Bzh[o + 1]);
                MMA16816(aZ[tm][tn], Al[tm], Bzh[o], Bzh[o + 1]);
                MMA16816(aZ[tm][tn], Ah[tm], Bzl[o], Bzl[o + 1]);
                MMA16816(aH[tm][tn], Ah[tm], Bhh[o], Bhh[o + 1]);
                MMA16816(aH[tm][tn], Al[tm], Bhh[o], Bhh[o + 1]);
                MMA16816(aH[tm][tn], Ah[tm], Bhl[o], Bhl[o + 1]);
            }
    }
}

#define ZERO_ACC224(acc) \
    { _Pragma("unroll") for (int i = 0; i < 2; i++) \
      _Pragma("unroll") for (int j = 0; j < 2; j++) \
      _Pragma("unroll") for (int q = 0; q < 4; q++) (acc)[i][j][q] = 0.f; }

__global__ void __launch_bounds__(512, 1) enc_gates() {
    extern __shared__ char sm[];
    uint32_t sb = smem_u32(sm);
    int tid = threadIdx.x, lane = tid & 31, wid = tid >> 5;
    int wm = wid & 1, wn = wid >> 1;

    copy_w_swz(sm, 0, tid, EWE_HI, EWE_LO);
    copy_w_swz(sm, 1, tid, EWZ_HI, EWZ_LO);
    copy_w_swz(sm, 3, tid, EWH_HI, EWH_LO);

    int xrow = tid >> 3, xseg = (tid & 7) * 16;
    int xc0 = xseg >> 3;

    float4 pf[4];
    {
        int tt = blockIdx.x;
        int t = tt / NTIL64, tile = tt - t * NTIL64;
        const float4* s = (const float4*)(g_agg + ((size_t)t * NRP + tile * 64 + xrow) * D + xseg);
#pragma unroll
        for (int q = 0; q < 4; q++) pf[q] = s[q];
    }

    for (int tt = blockIdx.x; tt < NTT; tt += gridDim.x) {
        int t = tt / NTIL64, tile = tt - t * NTIL64;

        __syncthreads();
#pragma unroll
        for (int g = 0; g < 2; g++) {
            float4 a = pf[g * 2], b = pf[g * 2 + 1];
            uint32_t h0, h1, h2, h3, l0, l1, l2, l3;
            split2(a.x, a.y, h0, l0);
            split2(a.z, a.w, h1, l1);
            split2(b.x, b.y, h2, l2);
            split2(b.z, b.w, h3, l3);
            uint32_t off = (uint32_t)(xrow * 256) + ((((xc0 + g) ^ (xrow & 7)) & 15) << 4);
            *(uint4*)(sm + EX_HI + off) = make_uint4(h0, h1, h2, h3);
            *(uint4*)(sm + EX_LO + off) = make_uint4(l0, l1, l2, l3);
        }
        __syncthreads();

        float acc[2][2][4];
        ZERO_ACC224(acc);
        gemm64sw(acc, sb + EX_HI, sb + EX_LO, sb + EWE_HI, sb + EWE_LO, lane, wm, wn);
        __syncthreads();

#pragma unroll
        for (int tm = 0; tm < 2; tm++)
#pragma unroll
            for (int tn = 0; tn < 2; tn++) {
                int c = wn * 16 + tn * 8 + (lane & 3) * 2;
#pragma unroll
                for (int h2i = 0; h2i < 2; h2i++) {
                    int r = wm * 32 + tm * 16 + (lane >> 2) + h2i * 8;
                    uint32_t h, l;
                    split2(ftanh(acc[tm][tn][h2i * 2]), ftanh(acc[tm][tn][h2i * 2 + 1]), h, l);
                    uint32_t off = (uint32_t)(r * 256) + ((((c >> 3) ^ (r & 7)) & 15) << 4)
                                 + (uint32_t)((c & 7) * 2);
                    *(uint32_t*)(sm + EX_HI + off) = h;
                    *(uint32_t*)(sm + EX_LO + off) = l;
                }
            }
        __syncthreads();

        if (tt + (int)gridDim.x < NTT) {
            int nt2 = tt + gridDim.x;
            int t2 = nt2 / NTIL64, tile2 = nt2 - t2 * NTIL64;
            const float4* s = (const float4*)(g_agg + ((size_t)t2 * NRP + tile2 * 64 + xrow) * D + xseg);
#pragma unroll
            for (int q = 0; q < 4; q++) pf[q] = s[q];
        }

        float accZ[2][2][4], accH[2][2][4];
        ZERO_ACC224(accZ);
        ZERO_ACC224(accH);
        gemm64sw_dual(accZ, accH, sb + EX_HI, sb + EX_LO,
                      sb + EWZ_HI, sb + EWZ_LO, sb + EWH_HI, sb + EWH_LO, lane, wm, wn);

        size_t base = (size_t)t * NRP + (size_t)tile * 64;
#pragma unroll
        for (int tm = 0; tm < 2; tm++)
#pragma unroll
            for (int tn = 0; tn < 2; tn++) {
                int c = wn * 16 + tn * 8 + (lane & 3) * 2;
#pragma unroll
                for (int h2i = 0; h2i < 2; h2i++) {
                    int r = wm * 32 + tm * 16 + (lane >> 2) + h2i * 8;
                    __half2 hz = __floats2half2_rn(accZ[tm][tn][h2i * 2], accZ[tm][tn][h2i * 2 + 1]);
                    __half2 hh = __floats2half2_rn(accH[tm][tn][h2i * 2], accH[tm][tn][h2i * 2 + 1]);
                    *(__half2*)(g_GZ + (base + r) * D + c) = hz;
                    *(__half2*)(g_GH + (base + r) * D + c) = hh;
                }
            }
    }
}

// ---------------------------------------------------------------------------
// step_all: 2 groups/CTA x 2 wm-halves = 4 sync domains (named bar.sync, 128
// thr). Group owns a 32-row tile stream; warp tile 16m x 32n. State in
// registers across t; gz/gh loaded as fp16 (early-issued).
// ---------------------------------------------------------------------------
__device__ __forceinline__ void copy_w_pad(char* sm_, int w, int tid,
                                           int hi_off, int lo_off) {
    const uint4* s = g_Wp + (size_t)w * 4096;
    for (int i = tid; i < 4096; i += 512) {
        int sp = i >> 11, j = i & 2047, n = j >> 4, kk = j & 15;
        *(uint4*)(sm_ + (sp ? lo_off : hi_off) + (uint32_t)(n * PAD + kk * 8) * 2) = s[i];
    }
}

__device__ __forceinline__ void gemm_step_dual(float (&aZ)[4][4], float (&aH)[4][4],
                                               uint32_t xhi, uint32_t xlo,
                                               uint32_t zhi, uint32_t zlo,
                                               uint32_t hhi, uint32_t hlo,
                                               int lane, int wm, int wn) {
    const int arow = wm * 16 + (lane & 15);
    const int acolo = (lane >> 4) * 8;
    const int brow = wn * 32 + (lane & 7) + ((lane >> 4) & 1) * 8;
    const int bcolo = ((lane >> 3) & 1) * 8;
    const uint32_t bstep = (uint32_t)(16 * PAD) * 2;
#pragma unroll 1
    for (int ks = 0; ks < 8; ks++) {
        uint32_t Ah[4], Al[4], Bzh[8], Bzl[8], Bhh[8], Bhl[8];
        uint32_t ao = (uint32_t)(arow * PAD + ks * 16 + acolo) * 2;
        uint32_t bo = (uint32_t)(brow * PAD + ks * 16 + bcolo) * 2;
        LDSM4(Ah, xhi + ao);
        LDSM4(Al, xlo + ao);
        LDSM4(Bzh, zhi + bo);
        LDSM4(Bzh + 4, zhi + bo + bstep);
        LDSM4(Bzl, zlo + bo);
        LDSM4(Bzl + 4, zlo + bo + bstep);
        LDSM4(Bhh, hhi + bo);
        LDSM4(Bhh + 4, hhi + bo + bstep);
        LDSM4(Bhl, hlo + bo);
        LDSM4(Bhl + 4, hlo + bo + bstep);
#pragma unroll
        for (int tn = 0; tn < 4; tn++) {
            int o = tn * 2;
            MMA16816(aZ[tn], Ah, Bzh[o], Bzh[o + 1]);
            MMA16816(aZ[tn], Al, Bzh[o], Bzh[o + 1]);
            MMA16816(aZ[tn], Ah, Bzl[o], Bzl[o + 1]);
            MMA16816(aH[tn], Ah, Bhh[o], Bhh[o + 1]);
            MMA16816(aH[tn], Al, Bhh[o], Bhh[o + 1]);
            MMA16816(aH[tn], Ah, Bhl[o], Bhl[o + 1]);
        }
    }
}

__global__ void __launch_bounds__(512, 1) step_all(const float* __restrict__ bz,
                                                   const float* __restrict__ bh,
                                                   float* __restrict__ out) {
    extern __shared__ char sm[];
    uint32_t sb = smem_u32(sm);
    int tid = threadIdx.x, lane = tid & 31, wid = tid >> 5;
    int grp = wid >> 3;
    int lw = wid & 7;
    int wm = lw & 1, wn = lw >> 1;
    int barid = 1 + grp * 2 + wm;

    copy_w_pad(sm, 2, tid, SW0_HI, SW0_LO);  // Uz
    copy_w_pad(sm, 4, tid, SW1_HI, SW1_LO);  // Uh

    uint32_t sxhi = sb + SXBASE + grp * SXG;
    uint32_t sxlo = sxhi + 8704;

    int cols[4];
#pragma unroll
    for (int tn = 0; tn < 4; tn++) cols[tn] = wn * 32 + tn * 8 + (lane & 3) * 2;
    int rowsl[2];
#pragma unroll
    for (int h2 = 0; h2 < 2; h2++) rowsl[h2] = wm * 16 + (lane >> 2) + h2 * 8;

    float2 bzv[4], bhv[4];
#pragma unroll
    for (int tn = 0; tn < 4; tn++) {
        bzv[tn] = *(const float2*)(bz + cols[tn]);
        bhv[tn] = *(const float2*)(bh + cols[tn]);
    }
    __syncthreads();  // weights ready (only full-CTA barrier)

    for (int tile = blockIdx.x * 2 + grp; tile < NTIL32; tile += 296) {
        float S[4][4];
#pragma unroll
        for (int tn = 0; tn < 4; tn++)
#pragma unroll
            for (int q = 0; q < 4; q++) S[tn][q] = 0.f;

        for (int t = 0; t < NT; t++) {
            size_t base = (size_t)t * NRP + (size_t)tile * 32;
            float2 gz[4][2], gh[4][2];
#pragma unroll
            for (int tn = 0; tn < 4; tn++)
#pragma unroll
                for (int h2 = 0; h2 < 2; h2++) {
                    size_t idx = (base + rowsl[h2]) * D + cols[tn];
                    gz[tn][h2] = __half22float2(*(const __half2*)(g_GZ + idx));
                    gh[tn][h2] = __half22float2(*(const __half2*)(g_GH + idx));
                }

            float aZ[4][4], aH[4][4];
#pragma unroll
            for (int tn = 0; tn < 4; tn++)
#pragma unroll
                for (int q = 0; q < 4; q++) { aZ[tn][q] = 0.f; aH[tn][q] = 0.f; }

            if (t > 0) {
#pragma unroll
                for (int tn = 0; tn < 4; tn++)
#pragma unroll
                    for (int h2 = 0; h2 < 2; h2++) {
                        uint32_t h, l;
                        split2(S[tn][h2 * 2], S[tn][h2 * 2 + 1], h, l);
                        uint32_t off = (uint32_t)(rowsl[h2] * PAD + cols[tn]) * 2;
                        *(uint32_t*)(sm + SXBASE + grp * SXG + off) = h;
                        *(uint32_t*)(sm + SXBASE + grp * SXG + 8704 + off) = l;
                    }
                BARH(barid);
                gemm_step_dual(aZ, aH, sxhi, sxlo,
                               sb + SW0_HI, sb + SW0_LO, sb + SW1_HI, sb + SW1_LO,
                               lane, wm, wn);
            }

#pragma unroll
            for (int tn = 0; tn < 4; tn++)
#pragma unroll
                for (int h2 = 0; h2 < 2; h2++) {
                    float z0 = fsig(gz[tn][h2].x + aZ[tn][h2 * 2]     + bzv[tn].x);
                    float z1 = fsig(gz[tn][h2].y + aZ[tn][h2 * 2 + 1] + bzv[tn].y);
                    float c0 = ftanh(gh[tn][h2].x + aH[tn][h2 * 2]     + bhv[tn].x);
                    float c1 = ftanh(gh[tn][h2].y + aH[tn][h2 * 2 + 1] + bhv[tn].y);
                    S[tn][h2 * 2]     = (1.f - z0) * S[tn][h2 * 2]     + z0 * c0;
                    S[tn][h2 * 2 + 1] = (1.f - z1) * S[tn][h2 * 2 + 1] + z1 * c1;
                }
            if (t > 0 && t + 1 < NT) BARH(barid);
        }

#pragma unroll
        for (int tn = 0; tn < 4; tn++)
#pragma unroll
            for (int h2 = 0; h2 < 2; h2++) {
                int grow = tile * 32 + rowsl[h2];
                *(float2*)(out + (size_t)grow * D + cols[tn]) =
                    make_float2(S[tn][h2 * 2], S[tn][h2 * 2 + 1]);
            }
    }
}

// ---------------------------------------------------------------------------
extern "C" void kernel_launch(void* const* d_in, const int* in_sizes, int n_in,
                              void* d_out, int out_size) {
    const int*   ei       = (const int*)d_in[0];
    const int*   src      = ei;
    const int*   dst      = ei + NE;
    const int*   etype    = (const int*)d_in[1];
    const int*   etime    = (const int*)d_in[2];
    const float* ew       = (const float*)d_in[3];
    const float* node_emb = (const float*)d_in[4];
    const float* rel_emb  = (const float*)d_in[5];
    const float* Wenc     = (const float*)d_in[6];
    const float* Wz       = (const float*)d_in[7];
    const float* Uz       = (const float*)d_in[8];
    const float* Wh       = (const float*)d_in[9];
    const float* Uh       = (const float*)d_in[10];
    const float* bz       = (const float*)d_in[11];
    const float* bh       = (const float*)d_in[12];

    cudaFuncSetAttribute(enc_gates, cudaFuncAttributeMaxDynamicSharedMemorySize, SMEM_ENC);
    cudaFuncSetAttribute(step_all,  cudaFuncAttributeMaxDynamicSharedMemorySize, SMEM_STEP);

    void* aggp = nullptr;
    cudaGetSymbolAddress(&aggp, g_agg);
    cudaMemsetAsync(aggp, 0, (size_t)NT * NRP * D * sizeof(float), 0);

    prep_weights<<<(5 * 128 * 128 + 255) / 256, 256>>>(Wenc, Wz, Uz, Wh, Uh);
    scatter_kernel<<<(NE * 32 + 255) / 256, 256>>>(src, dst, etype, etime, ew,
                                                   node_emb, rel_emb);

    enc_gates<<<148, 512, SMEM_ENC>>>();
    step_all<<<148, 512, SMEM_STEP>>>(bz, bh, (float*)d_out);
}